// round 3
// baseline (speedup 1.0000x reference)
#include <cuda_runtime.h>
#include <cuda_bf16.h>
#include <cstdint>

// Problem constants (fixed by the dataset).
#define NNODES   50000
#define NEDGES   800000
#define F_IN     128
#define F_HID    128
#define F_OUT    64
#define NREL     8
#define NC1      (F_HID + NREL * F_HID)   // 1152 packed output cols, layer 1
#define NC2      (F_OUT + NREL * F_OUT)   // 576  packed output cols, layer 2

// ---------------- scratch (static device globals; no allocation) ------------
__device__ __align__(128) float g_buf1[(size_t)NNODES * NC1];  // 230.4 MB, reused by layer 2
__device__ __align__(128) float g_h   [(size_t)NNODES * F_HID]; // hidden activations
__device__ __align__(128) float g_inv [NNODES * NREL];
__device__ __align__(128) int   g_cnt [NNODES * NREL];
__device__ __align__(128) float g_B1  [F_IN  * NC1];           // packed [root1 | W1[0..7]]
__device__ __align__(128) float g_B2  [F_HID * NC2];           // packed [root2 | W2[0..7]]

// ---------------- graph-structure kernels ------------------------------------
__global__ void k_zero_cnt(int n) {
    int i = blockIdx.x * blockDim.x + threadIdx.x;
    if (i < n) g_cnt[i] = 0;
}

// NOTE: edge arrays are int32 (JAX default x64=False downcasts jnp.int64 -> int32)
__global__ void k_count(const int* __restrict__ dst,
                        const int* __restrict__ et, int E) {
    int e = blockIdx.x * blockDim.x + threadIdx.x;
    if (e >= E) return;
    int d = dst[e];
    int r = et[e];
    atomicAdd(&g_cnt[d * NREL + r], 1);
}

__global__ void k_inv(int n) {
    int i = blockIdx.x * blockDim.x + threadIdx.x;
    if (i >= n) return;
    int c = g_cnt[i];
    g_inv[i] = 1.0f / (float)(c > 1 ? c : 1);
}

// ---------------- weight packing ---------------------------------------------
__global__ void k_packB1(const float* __restrict__ root1, const float* __restrict__ W1) {
    int idx = blockIdx.x * blockDim.x + threadIdx.x;
    if (idx >= F_IN * NC1) return;
    int k = idx / NC1, c = idx % NC1;
    float v;
    if (c < F_HID) v = root1[k * F_HID + c];
    else {
        int r = (c - F_HID) >> 7, j = (c - F_HID) & 127;
        v = W1[((size_t)r * F_IN + k) * F_HID + j];
    }
    g_B1[idx] = v;
}

__global__ void k_packB2(const float* __restrict__ root2, const float* __restrict__ W2) {
    int idx = blockIdx.x * blockDim.x + threadIdx.x;
    if (idx >= F_HID * NC2) return;
    int k = idx / NC2, c = idx % NC2;
    float v;
    if (c < F_OUT) v = root2[k * F_OUT + c];
    else {
        int r = (c - F_OUT) >> 6, j = (c - F_OUT) & 63;
        v = W2[((size_t)r * F_HID + k) * F_OUT + j];
    }
    g_B2[idx] = v;
}

// ---------------- fp32 SIMT GEMM, K=128 fixed --------------------------------
// C[M, Ncols] = A[M,128] @ B[128, Ncols] (+ bias on cols < biasN)
// A selected by a_sel: 0 -> Aext (input x), 1 -> g_h. B by b_sel: 1 -> g_B1, 2 -> g_B2.
// C is always g_buf1. BM=BN=128, BK=16, 256 threads, 8x8 microtile.
__global__ __launch_bounds__(256, 2)
void k_gemm_k128(const float* __restrict__ Aext, int a_sel, int b_sel,
                 const float* __restrict__ bias,
                 int M, int Ncols, int biasN) {
    const float* A = (a_sel == 0) ? Aext : &g_h[0];
    const float* B = (b_sel == 1) ? &g_B1[0] : &g_B2[0];
    float*       C = &g_buf1[0];

    __shared__ float As[16][128];
    __shared__ float Bs[16][128];

    const int tid = threadIdx.x;
    const int tx = tid & 15, ty = tid >> 4;
    const int m0 = blockIdx.y * 128, n0 = blockIdx.x * 128;

    const int a_row = tid >> 1;             // 0..127
    const int kq0   = (tid & 1) * 2;        // float4 index within 16-wide K slab
    const int b_col = tx * 8;

    float acc[8][8];
#pragma unroll
    for (int i = 0; i < 8; i++)
#pragma unroll
        for (int j = 0; j < 8; j++) acc[i][j] = 0.0f;

    for (int k0 = 0; k0 < 128; k0 += 16) {
        {
            int gm = m0 + a_row;
            float4 v0 = make_float4(0.f, 0.f, 0.f, 0.f);
            float4 v1 = v0;
            if (gm < M) {
                const float4* ap = (const float4*)(A + (size_t)gm * 128 + k0);
                v0 = ap[kq0];
                v1 = ap[kq0 + 1];
            }
            As[kq0 * 4 + 0][a_row] = v0.x;
            As[kq0 * 4 + 1][a_row] = v0.y;
            As[kq0 * 4 + 2][a_row] = v0.z;
            As[kq0 * 4 + 3][a_row] = v0.w;
            As[kq0 * 4 + 4][a_row] = v1.x;
            As[kq0 * 4 + 5][a_row] = v1.y;
            As[kq0 * 4 + 6][a_row] = v1.z;
            As[kq0 * 4 + 7][a_row] = v1.w;
        }
        {
            int gc = n0 + b_col;
            float4 v0 = make_float4(0.f, 0.f, 0.f, 0.f);
            float4 v1 = v0;
            if (gc < Ncols) {
                const float* bp = B + (size_t)(k0 + ty) * Ncols + gc;
                v0 = *(const float4*)(bp);
                v1 = *(const float4*)(bp + 4);
            }
            *(float4*)&Bs[ty][b_col]     = v0;
            *(float4*)&Bs[ty][b_col + 4] = v1;
        }
        __syncthreads();

#pragma unroll
        for (int k = 0; k < 16; k++) {
            float4 a0 = *(const float4*)&As[k][ty * 8];
            float4 a1 = *(const float4*)&As[k][ty * 8 + 4];
            float4 b0 = *(const float4*)&Bs[k][tx * 8];
            float4 b1 = *(const float4*)&Bs[k][tx * 8 + 4];
            float am[8] = {a0.x, a0.y, a0.z, a0.w, a1.x, a1.y, a1.z, a1.w};
            float bn[8] = {b0.x, b0.y, b0.z, b0.w, b1.x, b1.y, b1.z, b1.w};
#pragma unroll
            for (int i = 0; i < 8; i++)
#pragma unroll
                for (int j = 0; j < 8; j++) acc[i][j] += am[i] * bn[j];
        }
        __syncthreads();
    }

#pragma unroll
    for (int i = 0; i < 8; i++) {
        int gm = m0 + ty * 8 + i;
        if (gm >= M) continue;
        float* crow = C + (size_t)gm * Ncols;
#pragma unroll
        for (int j = 0; j < 8; j++) {
            int gc = n0 + tx * 8 + j;
            if (gc < Ncols) {
                float v = acc[i][j];
                if (gc < biasN) v += bias[gc];
                crow[gc] = v;
            }
        }
    }
}

// ---------------- edge scatter, layer 1 (F=128, warp per edge) ---------------
__global__ void k_scatter1(const int* __restrict__ src,
                           const int* __restrict__ dst,
                           const int* __restrict__ et, int E) {
    int w = (blockIdx.x * blockDim.x + threadIdx.x) >> 5;
    int lane = threadIdx.x & 31;
    if (w >= E) return;
    int s = src[w], d = dst[w], r = et[w];
    float sc = g_inv[d * NREL + r];
    const float4* rp = (const float4*)(g_buf1 + (size_t)s * NC1 + F_HID + (size_t)r * F_HID);
    float4 v = rp[lane];
    float* ap = g_buf1 + (size_t)d * NC1 + lane * 4;
    atomicAdd(ap + 0, v.x * sc);
    atomicAdd(ap + 1, v.y * sc);
    atomicAdd(ap + 2, v.z * sc);
    atomicAdd(ap + 3, v.w * sc);
}

// ---------------- edge scatter, layer 2 (F=64, half-warp per edge) -----------
__global__ void k_scatter2(const int* __restrict__ src,
                           const int* __restrict__ dst,
                           const int* __restrict__ et, int E) {
    int t = blockIdx.x * blockDim.x + threadIdx.x;
    int e = t >> 4;
    int sub = t & 15;
    if (e >= E) return;
    int s = src[e], d = dst[e], r = et[e];
    float sc = g_inv[d * NREL + r];
    const float4* rp = (const float4*)(g_buf1 + (size_t)s * NC2 + F_OUT + (size_t)r * F_OUT);
    float4 v = rp[sub];
    float* ap = g_buf1 + (size_t)d * NC2 + sub * 4;
    atomicAdd(ap + 0, v.x * sc);
    atomicAdd(ap + 1, v.y * sc);
    atomicAdd(ap + 2, v.z * sc);
    atomicAdd(ap + 3, v.w * sc);
}

// ---------------- relu extract + final copy ----------------------------------
__global__ void k_relu(int total) {  // total = N * F_HID
    int i = blockIdx.x * blockDim.x + threadIdx.x;
    if (i >= total) return;
    int n = i >> 7, j = i & 127;
    float v = g_buf1[(size_t)n * NC1 + j];
    g_h[i] = v > 0.0f ? v : 0.0f;
}

__global__ void k_copy_out(float* __restrict__ out, int total) {  // total = N * F_OUT
    int i = blockIdx.x * blockDim.x + threadIdx.x;
    if (i >= total) return;
    int n = i >> 6, j = i & 63;
    out[i] = g_buf1[(size_t)n * NC2 + j];
}

// ---------------- launch -----------------------------------------------------
extern "C" void kernel_launch(void* const* d_in, const int* in_sizes, int n_in,
                              void* d_out, int out_size) {
    const float* x     = (const float*)d_in[0];
    const int*   ei    = (const int*)d_in[1];   // [2, E] int32 (JAX x64 disabled)
    const int*   et    = (const int*)d_in[2];   // [E]    int32
    const float* W1    = (const float*)d_in[3];
    const float* root1 = (const float*)d_in[4];
    const float* b1    = (const float*)d_in[5];
    const float* W2    = (const float*)d_in[6];
    const float* root2 = (const float*)d_in[7];
    const float* b2    = (const float*)d_in[8];
    float*       out   = (float*)d_out;

    const int N = in_sizes[0] / F_IN;
    const int E = in_sizes[2];
    const int* src = ei;
    const int* dst = ei + E;

    // graph structure (counts -> reciprocal means), same for both layers
    k_zero_cnt<<<(N * NREL + 255) / 256, 256>>>(N * NREL);
    k_count<<<(E + 255) / 256, 256>>>(dst, et, E);
    k_inv<<<(N * NREL + 255) / 256, 256>>>(N * NREL);

    // pack weights
    k_packB1<<<(F_IN * NC1 + 255) / 256, 256>>>(root1, W1);
    k_packB2<<<(F_HID * NC2 + 255) / 256, 256>>>(root2, W2);

    // ---- layer 1 ----
    {
        dim3 grid((NC1 + 127) / 128, (N + 127) / 128);
        k_gemm_k128<<<grid, 256>>>(x, /*a_sel=*/0, /*b_sel=*/1, b1, N, NC1, F_HID);
    }
    k_scatter1<<<(E * 32 + 255) / 256, 256>>>(src, dst, et, E);
    k_relu<<<(N * F_HID + 255) / 256, 256>>>(N * F_HID);

    // ---- layer 2 ----
    {
        dim3 grid((NC2 + 127) / 128, (N + 127) / 128);
        k_gemm_k128<<<grid, 256>>>(nullptr, /*a_sel=*/1, /*b_sel=*/2, b2, N, NC2, F_OUT);
    }
    k_scatter2<<<(E * 16 + 255) / 256, 256>>>(src, dst, et, E);
    k_copy_out<<<(N * F_OUT + 255) / 256, 256>>>(out, N * F_OUT);
}

// round 5
// speedup vs baseline: 1.8371x; 1.8371x over previous
#include <cuda_runtime.h>
#include <cuda_bf16.h>
#include <cstdint>

// Problem constants (fixed by the dataset).
#define NNODES   50000
#define F_IN     128
#define F_HID    128
#define F_OUT    64
#define NREL     8
#define NC1      1152     // 128 root + 8*128 messages (layer 1 packed cols)
#define NC2      576      // 64 root + 8*64 (layer 2)
#define NPAD2    640      // NC2 padded to multiple of 128

// ---------------- scratch (static device globals; no allocation) -------------
__device__ __align__(128) float g_buf1[(size_t)NNODES * NC1];   // 230 MB, GEMM out + scatter acc
__device__ __align__(128) float g_inv [NNODES * NREL];
__device__ __align__(128) int   g_cnt [NNODES * NREL];
__device__ __align__(256) __nv_bfloat16 g_Ahi[(size_t)NNODES * 128];
__device__ __align__(256) __nv_bfloat16 g_Alo[(size_t)NNODES * 128];
__device__ __align__(256) __nv_bfloat16 g_B1hi[NC1 * 128];   // transposed Bt[n][k]
__device__ __align__(256) __nv_bfloat16 g_B1lo[NC1 * 128];
__device__ __align__(256) __nv_bfloat16 g_B2hi[NPAD2 * 128];
__device__ __align__(256) __nv_bfloat16 g_B2lo[NPAD2 * 128];

// ---------------- PTX helpers (plain sm_103-target ISA only) ------------------
__device__ __forceinline__ uint32_t s2u(const void* p) {
    return (uint32_t)__cvta_generic_to_shared(p);
}
__device__ __forceinline__ void ldm_x4(uint32_t* r, uint32_t addr) {
    asm volatile("ldmatrix.sync.aligned.m8n8.x4.shared.b16 {%0,%1,%2,%3}, [%4];"
                 : "=r"(r[0]), "=r"(r[1]), "=r"(r[2]), "=r"(r[3]) : "r"(addr));
}
__device__ __forceinline__ void mma16816(float* c, const uint32_t* a, const uint32_t* b) {
    asm volatile("mma.sync.aligned.m16n8k16.row.col.f32.bf16.bf16.f32 "
                 "{%0,%1,%2,%3}, {%4,%5,%6,%7}, {%8,%9}, {%0,%1,%2,%3};"
                 : "+f"(c[0]), "+f"(c[1]), "+f"(c[2]), "+f"(c[3])
                 : "r"(a[0]), "r"(a[1]), "r"(a[2]), "r"(a[3]), "r"(b[0]), "r"(b[1]));
}
__device__ __forceinline__ void red4(float* p, float a, float b, float c, float d) {
    asm volatile("red.global.add.v4.f32 [%0], {%1,%2,%3,%4};"
                 :: "l"(p), "f"(a), "f"(b), "f"(c), "f"(d) : "memory");
}

// ---------------- graph-structure kernels ------------------------------------
__global__ void k_zero_cnt(int n) {
    int i = blockIdx.x * blockDim.x + threadIdx.x;
    if (i < n) g_cnt[i] = 0;
}
__global__ void k_count(const int* __restrict__ dst, const int* __restrict__ et, int E) {
    int e = blockIdx.x * blockDim.x + threadIdx.x;
    if (e >= E) return;
    atomicAdd(&g_cnt[dst[e] * NREL + et[e]], 1);
}
__global__ void k_inv(int n) {
    int i = blockIdx.x * blockDim.x + threadIdx.x;
    if (i >= n) return;
    int c = g_cnt[i];
    g_inv[i] = 1.0f / (float)(c > 1 ? c : 1);
}

// ---------------- weight packing (transposed Bt[n][k], bf16 hi/lo split) -----
__global__ void k_packB1(const float* __restrict__ root1, const float* __restrict__ W1) {
    int idx = blockIdx.x * blockDim.x + threadIdx.x;
    if (idx >= NC1 * 128) return;
    int n = idx >> 7, k = idx & 127;
    float v;
    if (n < F_HID) v = root1[k * F_HID + n];
    else {
        int r = (n - F_HID) >> 7, j = (n - F_HID) & 127;
        v = W1[((size_t)r * F_IN + k) * F_HID + j];
    }
    __nv_bfloat16 h = __float2bfloat16(v);
    g_B1hi[idx] = h;
    g_B1lo[idx] = __float2bfloat16(v - __bfloat162float(h));
}
__global__ void k_packB2(const float* __restrict__ root2, const float* __restrict__ W2) {
    int idx = blockIdx.x * blockDim.x + threadIdx.x;
    if (idx >= NPAD2 * 128) return;
    int n = idx >> 7, k = idx & 127;
    float v = 0.0f;
    if (n < NC2) {
        if (n < F_OUT) v = root2[k * F_OUT + n];
        else {
            int r = (n - F_OUT) >> 6, j = (n - F_OUT) & 63;
            v = W2[((size_t)r * F_HID + k) * F_OUT + j];
        }
    }
    __nv_bfloat16 h = __float2bfloat16(v);
    g_B2hi[idx] = h;
    g_B2lo[idx] = __float2bfloat16(v - __bfloat162float(h));
}

// ---------------- bf16 hi/lo splits of activations ---------------------------
__global__ void k_split_x(const float* __restrict__ x, int total) {
    int i = blockIdx.x * blockDim.x + threadIdx.x;
    if (i >= total) return;
    float v = x[i];
    __nv_bfloat16 h = __float2bfloat16(v);
    g_Ahi[i] = h;
    g_Alo[i] = __float2bfloat16(v - __bfloat162float(h));
}
__global__ void k_relu_split(int total) {  // total = N * F_HID
    int i = blockIdx.x * blockDim.x + threadIdx.x;
    if (i >= total) return;
    int n = i >> 7, j = i & 127;
    float v = g_buf1[(size_t)n * NC1 + j];
    v = v > 0.0f ? v : 0.0f;
    __nv_bfloat16 h = __float2bfloat16(v);
    g_Ahi[i] = h;
    g_Alo[i] = __float2bfloat16(v - __bfloat162float(h));
}

// ---------------- bf16-split HMMA GEMM ---------------------------------------
// C[M, Ncols] = (Ahi+Alo)[M,128] @ (Bhi+Blo)t, + bias cols < biasN.
// Block 128x128, K chunked by 64. 8 warps: wm = w&1 (2 M-warps of 64),
// wn = w>>1 (4 N-warps of 32). Warp tile 64x32 = 4x4 m16n8 frags.
#define AS_STRIDE 72   // bf16 per SMEM row (64 data + 8 pad -> conflict-free ldmatrix)

__global__ __launch_bounds__(256, 2)
void k_gemm_hmma(int b_sel, const float* __restrict__ bias,
                 int M, int Ncols, int biasN) {
    __shared__ __nv_bfloat16 As[128 * AS_STRIDE];
    __shared__ __nv_bfloat16 Bs[128 * AS_STRIDE];
    __shared__ float sBias[128];

    const __nv_bfloat16* Bhi = (b_sel == 1) ? &g_B1hi[0] : &g_B2hi[0];
    const __nv_bfloat16* Blo = (b_sel == 1) ? &g_B1lo[0] : &g_B2lo[0];
    float* C = &g_buf1[0];

    const int tid  = threadIdx.x;
    const int wid  = tid >> 5;
    const int lane = tid & 31;
    const int wm   = wid & 1;
    const int wn   = wid >> 1;
    const int n0 = blockIdx.x * 128;
    const int m0 = blockIdx.y * 128;

    if (tid < 128) {
        int gc = n0 + tid;
        sBias[tid] = (gc < biasN) ? bias[gc] : 0.0f;
    }

    float acc[4][4][4];
#pragma unroll
    for (int i = 0; i < 4; i++)
#pragma unroll
        for (int j = 0; j < 4; j++)
#pragma unroll
            for (int q = 0; q < 4; q++) acc[i][j][q] = 0.0f;

    // ldmatrix source addresses (byte offsets into As/Bs)
    const uint32_t asBase = s2u(As), bsBase = s2u(Bs);
    const int aRow = wm * 64 + (lane & 15);
    const int aCol = ((lane >> 4) & 1) * 8;
    const int bRow = wn * 32 + (lane & 7) + ((lane & 16) ? 8 : 0);
    const int bCol = (lane & 8) ? 8 : 0;

    // loader mapping: 1024 16B-chunks per tile, 4 per thread per tile
    const int lr = tid >> 1;                 // not used; keep loads simple below

#pragma unroll 1
    for (int pass = 0; pass < 3; pass++) {
        const __nv_bfloat16* Asrc = (pass < 2) ? &g_Ahi[0] : &g_Alo[0];
        const __nv_bfloat16* Bsrc = (pass == 1) ? Blo : Bhi;
#pragma unroll 1
        for (int kc = 0; kc < 2; kc++) {
            const int kbase = kc * 64;
            __syncthreads();
            // load A,B tiles: 128 rows x 8 chunks each
            for (int c = tid; c < 1024; c += 256) {
                int r = c >> 3, ch = c & 7;
                int gm = m0 + r;
                uint4 va = make_uint4(0, 0, 0, 0);
                if (gm < M)
                    va = *(const uint4*)(&Asrc[(size_t)gm * 128 + kbase + ch * 8]);
                *(uint4*)(&As[r * AS_STRIDE + ch * 8]) = va;
                int gn = n0 + r;  // B rows padded to tile grid; always valid
                uint4 vb = *(const uint4*)(&Bsrc[(size_t)gn * 128 + kbase + ch * 8]);
                *(uint4*)(&Bs[r * AS_STRIDE + ch * 8]) = vb;
            }
            __syncthreads();

#pragma unroll
            for (int ks = 0; ks < 4; ks++) {
                uint32_t bfr[4][2];
                {
                    uint32_t t[4];
                    ldm_x4(t, bsBase + (uint32_t)((bRow) * AS_STRIDE + ks * 16 + bCol) * 2);
                    bfr[0][0] = t[0]; bfr[0][1] = t[1];
                    bfr[1][0] = t[2]; bfr[1][1] = t[3];
                    ldm_x4(t, bsBase + (uint32_t)((bRow + 16) * AS_STRIDE + ks * 16 + bCol) * 2);
                    bfr[2][0] = t[0]; bfr[2][1] = t[1];
                    bfr[3][0] = t[2]; bfr[3][1] = t[3];
                }
#pragma unroll
                for (int mt = 0; mt < 4; mt++) {
                    uint32_t afr[4];
                    ldm_x4(afr, asBase + (uint32_t)((aRow + mt * 16) * AS_STRIDE + ks * 16 + aCol) * 2);
#pragma unroll
                    for (int nt = 0; nt < 4; nt++)
                        mma16816(acc[mt][nt], afr, bfr[nt]);
                }
            }
        }
    }

    __syncthreads();
    // epilogue: c0,c1 -> (row, col..col+1), c2,c3 -> (row+8, col..col+1)
    const int quad = lane >> 2, tq = lane & 3;
#pragma unroll
    for (int mt = 0; mt < 4; mt++) {
        int row = m0 + wm * 64 + mt * 16 + quad;
#pragma unroll
        for (int nt = 0; nt < 4; nt++) {
            int colL = wn * 32 + nt * 8 + tq * 2;
            int gc = n0 + colL;
            if (gc < Ncols) {
                float b0 = sBias[colL], b1 = sBias[colL + 1];
                if (row < M) {
                    float2 v0 = make_float2(acc[mt][nt][0] + b0, acc[mt][nt][1] + b1);
                    *(float2*)(&C[(size_t)row * Ncols + gc]) = v0;
                }
                if (row + 8 < M) {
                    float2 v1 = make_float2(acc[mt][nt][2] + b0, acc[mt][nt][3] + b1);
                    *(float2*)(&C[(size_t)(row + 8) * Ncols + gc]) = v1;
                }
            }
        }
    }
}

// ---------------- edge scatter, layer 1 (F=128, warp per edge) ---------------
__global__ void k_scatter1(const int* __restrict__ src, const int* __restrict__ dst,
                           const int* __restrict__ et, int E) {
    int w = (blockIdx.x * blockDim.x + threadIdx.x) >> 5;
    int lane = threadIdx.x & 31;
    if (w >= E) return;
    int s = src[w], d = dst[w], r = et[w];
    float sc = g_inv[d * NREL + r];
    const float4* rp = (const float4*)(g_buf1 + (size_t)s * NC1 + F_HID + (size_t)r * F_HID);
    float4 v = rp[lane];
    float* ap = g_buf1 + (size_t)d * NC1 + lane * 4;
    red4(ap, v.x * sc, v.y * sc, v.z * sc, v.w * sc);
}

// ---------------- edge scatter, layer 2 (F=64, half-warp per edge) -----------
__global__ void k_scatter2(const int* __restrict__ src, const int* __restrict__ dst,
                           const int* __restrict__ et, int E) {
    int t = blockIdx.x * blockDim.x + threadIdx.x;
    int e = t >> 4, sub = t & 15;
    if (e >= E) return;
    int s = src[e], d = dst[e], r = et[e];
    float sc = g_inv[d * NREL + r];
    const float4* rp = (const float4*)(g_buf1 + (size_t)s * NC2 + F_OUT + (size_t)r * F_OUT);
    float4 v = rp[sub];
    float* ap = g_buf1 + (size_t)d * NC2 + sub * 4;
    red4(ap, v.x * sc, v.y * sc, v.z * sc, v.w * sc);
}

// ---------------- final copy --------------------------------------------------
__global__ void k_copy_out(float* __restrict__ out, int total) {  // total = N * F_OUT
    int i = blockIdx.x * blockDim.x + threadIdx.x;
    if (i >= total) return;
    int n = i >> 6, j = i & 63;
    out[i] = g_buf1[(size_t)n * NC2 + j];
}

// ---------------- launch -----------------------------------------------------
extern "C" void kernel_launch(void* const* d_in, const int* in_sizes, int n_in,
                              void* d_out, int out_size) {
    const float* x     = (const float*)d_in[0];
    const int*   ei    = (const int*)d_in[1];   // [2, E] int32 (JAX x64 disabled)
    const int*   et    = (const int*)d_in[2];   // [E]    int32
    const float* W1    = (const float*)d_in[3];
    const float* root1 = (const float*)d_in[4];
    const float* b1    = (const float*)d_in[5];
    const float* W2    = (const float*)d_in[6];
    const float* root2 = (const float*)d_in[7];
    const float* b2    = (const float*)d_in[8];
    float*       out   = (float*)d_out;

    const int N = in_sizes[0] / F_IN;
    const int E = in_sizes[2];
    const int* src = ei;
    const int* dst = ei + E;

    // graph structure
    k_zero_cnt<<<(N * NREL + 255) / 256, 256>>>(N * NREL);
    k_count<<<(E + 255) / 256, 256>>>(dst, et, E);
    k_inv<<<(N * NREL + 255) / 256, 256>>>(N * NREL);

    // weights + input split
    k_packB1<<<(NC1 * 128 + 255) / 256, 256>>>(root1, W1);
    k_packB2<<<(NPAD2 * 128 + 255) / 256, 256>>>(root2, W2);
    k_split_x<<<(N * F_IN + 255) / 256, 256>>>(x, N * F_IN);

    const int tilesM = (N + 127) / 128;

    // ---- layer 1 ----
    {
        dim3 grid(NC1 / 128, tilesM);
        k_gemm_hmma<<<grid, 256>>>(1, b1, N, NC1, F_HID);
    }
    k_scatter1<<<(E * 32 + 255) / 256, 256>>>(src, dst, et, E);
    k_relu_split<<<(N * F_HID + 255) / 256, 256>>>(N * F_HID);

    // ---- layer 2 ----
    {
        dim3 grid(NPAD2 / 128, tilesM);
        k_gemm_hmma<<<grid, 256>>>(2, b2, N, NC2, F_OUT);
    }
    k_scatter2<<<(E * 16 + 255) / 256, 256>>>(src, dst, et, E);
    k_copy_out<<<(N * F_OUT + 255) / 256, 256>>>(out, N * F_OUT);
}

// round 6
// speedup vs baseline: 1.9564x; 1.0649x over previous
#include <cuda_runtime.h>
#include <cuda_bf16.h>
#include <cstdint>

// Problem constants (fixed by the dataset).
#define NNODES   50000
#define NEDGES   800000
#define F_IN     128
#define F_HID    128
#define F_OUT    64
#define NREL     8
#define NC1      1152     // 128 root + 8*128 messages (layer 1 packed cols)
#define NC2      576      // 64 root + 8*64 (layer 2)
#define NPAD2    640      // NC2 padded to multiple of 128

// ---------------- scratch (static device globals; no allocation) -------------
__device__ __align__(128) float g_buf1[(size_t)NNODES * NC1];   // 230 MB, GEMM out + scatter acc
__device__ __align__(128) float g_inv [NNODES * NREL];
__device__ __align__(128) int   g_cnt [NNODES * NREL];
__device__ __align__(256) __nv_bfloat16 g_Ahi[(size_t)NNODES * 128];
__device__ __align__(256) __nv_bfloat16 g_Alo[(size_t)NNODES * 128];
__device__ __align__(256) __nv_bfloat16 g_B1hi[NC1 * 128];   // transposed Bt[n][k]
__device__ __align__(256) __nv_bfloat16 g_B1lo[NC1 * 128];
__device__ __align__(256) __nv_bfloat16 g_B2hi[NPAD2 * 128];
__device__ __align__(256) __nv_bfloat16 g_B2lo[NPAD2 * 128];
// edge sort (by src) structures
__device__ int   g_scnt[NNODES];
__device__ int   g_ptr [NNODES];
__device__ unsigned g_ega[NEDGES];   // src*8 + rel
__device__ int      g_egd[NEDGES];   // dst
__device__ float    g_esc[NEDGES];   // inv[dst*8+rel]

// ---------------- PTX helpers (plain sm_103-target ISA only) ------------------
__device__ __forceinline__ uint32_t s2u(const void* p) {
    return (uint32_t)__cvta_generic_to_shared(p);
}
__device__ __forceinline__ void ldm_x4(uint32_t* r, uint32_t addr) {
    asm volatile("ldmatrix.sync.aligned.m8n8.x4.shared.b16 {%0,%1,%2,%3}, [%4];"
                 : "=r"(r[0]), "=r"(r[1]), "=r"(r[2]), "=r"(r[3]) : "r"(addr));
}
__device__ __forceinline__ void mma16816(float* c, const uint32_t* a, const uint32_t* b) {
    asm volatile("mma.sync.aligned.m16n8k16.row.col.f32.bf16.bf16.f32 "
                 "{%0,%1,%2,%3}, {%4,%5,%6,%7}, {%8,%9}, {%0,%1,%2,%3};"
                 : "+f"(c[0]), "+f"(c[1]), "+f"(c[2]), "+f"(c[3])
                 : "r"(a[0]), "r"(a[1]), "r"(a[2]), "r"(a[3]), "r"(b[0]), "r"(b[1]));
}
__device__ __forceinline__ void red4(float* p, float a, float b, float c, float d) {
    asm volatile("red.global.add.v4.f32 [%0], {%1,%2,%3,%4};"
                 :: "l"(p), "f"(a), "f"(b), "f"(c), "f"(d) : "memory");
}

// ---------------- weight packing (merged; transposed Bt[n][k], hi/lo split) ---
__global__ void k_packB12(const float* __restrict__ root1, const float* __restrict__ W1,
                          const float* __restrict__ root2, const float* __restrict__ W2) {
    int idx = blockIdx.x * blockDim.x + threadIdx.x;
    if (idx < NC1 * 128) {
        int n = idx >> 7, k = idx & 127;
        float v;
        if (n < F_HID) v = root1[k * F_HID + n];
        else {
            int r = (n - F_HID) >> 7, j = (n - F_HID) & 127;
            v = W1[((size_t)r * F_IN + k) * F_HID + j];
        }
        __nv_bfloat16 h = __float2bfloat16(v);
        g_B1hi[idx] = h;
        g_B1lo[idx] = __float2bfloat16(v - __bfloat162float(h));
    } else {
        int i2 = idx - NC1 * 128;
        if (i2 >= NPAD2 * 128) return;
        int n = i2 >> 7, k = i2 & 127;
        float v = 0.0f;
        if (n < NC2) {
            if (n < F_OUT) v = root2[k * F_OUT + n];
            else {
                int r = (n - F_OUT) >> 6, j = (n - F_OUT) & 63;
                v = W2[((size_t)r * F_HID + k) * F_OUT + j];
            }
        }
        __nv_bfloat16 h = __float2bfloat16(v);
        g_B2hi[i2] = h;
        g_B2lo[i2] = __float2bfloat16(v - __bfloat162float(h));
    }
}

// ---------------- bf16 hi/lo splits of activations ---------------------------
__global__ void k_split_x(const float* __restrict__ x, int total) {
    int i = blockIdx.x * blockDim.x + threadIdx.x;
    if (i >= total) return;
    float v = x[i];
    __nv_bfloat16 h = __float2bfloat16(v);
    g_Ahi[i] = h;
    g_Alo[i] = __float2bfloat16(v - __bfloat162float(h));
}
__global__ void k_relu_split(int total) {  // total = N * F_HID
    int i = blockIdx.x * blockDim.x + threadIdx.x;
    if (i >= total) return;
    int n = i >> 7, j = i & 127;
    float v = g_buf1[(size_t)n * NC1 + j];
    v = v > 0.0f ? v : 0.0f;
    __nv_bfloat16 h = __float2bfloat16(v);
    g_Ahi[i] = h;
    g_Alo[i] = __float2bfloat16(v - __bfloat162float(h));
}

// ---------------- graph-structure kernels ------------------------------------
__global__ void k_zero(int nA, int nB) {   // zero g_cnt and g_scnt
    int i = blockIdx.x * blockDim.x + threadIdx.x;
    if (i < nA) g_cnt[i] = 0;
    if (i < nB) g_scnt[i] = 0;
}
__global__ void k_count(const int* __restrict__ src, const int* __restrict__ dst,
                        const int* __restrict__ et, int E) {
    int e = blockIdx.x * blockDim.x + threadIdx.x;
    if (e >= E) return;
    atomicAdd(&g_cnt[dst[e] * NREL + et[e]], 1);
    atomicAdd(&g_scnt[src[e]], 1);
}
__global__ void k_inv(int n) {
    int i = blockIdx.x * blockDim.x + threadIdx.x;
    if (i >= n) return;
    int c = g_cnt[i];
    g_inv[i] = 1.0f / (float)(c > 1 ? c : 1);
}
// single-block exclusive scan of g_scnt -> g_ptr (n <= 50176)
__global__ void k_scan(int n) {
    __shared__ int part[1024];
    int t = threadIdx.x;
    const int CH = (n + 1023) / 1024;
    int base = t * CH;
    int s = 0;
    for (int i = 0; i < CH; i++) { int idx = base + i; if (idx < n) s += g_scnt[idx]; }
    part[t] = s;
    __syncthreads();
    for (int off = 1; off < 1024; off <<= 1) {
        int v = (t >= off) ? part[t - off] : 0;
        __syncthreads();
        part[t] += v;
        __syncthreads();
    }
    int excl = (t == 0) ? 0 : part[t - 1];
    for (int i = 0; i < CH; i++) {
        int idx = base + i;
        if (idx < n) { g_ptr[idx] = excl; excl += g_scnt[idx]; }
    }
}
__global__ void k_fill(const int* __restrict__ src, const int* __restrict__ dst,
                       const int* __restrict__ et, int E) {
    int e = blockIdx.x * blockDim.x + threadIdx.x;
    if (e >= E) return;
    int s = src[e], d = dst[e], r = et[e];
    int pos = atomicAdd(&g_ptr[s], 1);
    g_ega[pos] = (unsigned)(s * NREL + r);
    g_egd[pos] = d;
    g_esc[pos] = g_inv[d * NREL + r];
}

// ---------------- bf16-split HMMA GEMM ---------------------------------------
// C[M, Ncols] = (Ahi+Alo)[M,128] @ (Bhi+Blo)t, + bias cols < biasN.
// Block 128x128. K chunked by 32; Ahi/Alo/Bhi/Blo tiles resident together,
// loaded once per chunk, 3 mma passes (hi*hi, hi*lo, lo*hi) run from SMEM.
// 8 warps: wm = w&1 (2 M-warps of 64), wn = w>>1 (4 N-warps of 32).
#define TS 40   // bf16 per SMEM row (32 data + 8 pad; conflict-free ldmatrix)

__global__ __launch_bounds__(256, 2)
void k_gemm_hmma(int b_sel, const float* __restrict__ bias,
                 int M, int Ncols, int biasN) {
    __shared__ __nv_bfloat16 sAhi[128 * TS], sAlo[128 * TS];
    __shared__ __nv_bfloat16 sBhi[128 * TS], sBlo[128 * TS];
    __shared__ float sBias[128];

    const __nv_bfloat16* Bhi = (b_sel == 1) ? &g_B1hi[0] : &g_B2hi[0];
    const __nv_bfloat16* Blo = (b_sel == 1) ? &g_B1lo[0] : &g_B2lo[0];
    float* C = &g_buf1[0];

    const int tid  = threadIdx.x;
    const int wid  = tid >> 5;
    const int lane = tid & 31;
    const int wm   = wid & 1;
    const int wn   = wid >> 1;
    const int n0 = blockIdx.x * 128;
    const int m0 = blockIdx.y * 128;

    if (tid < 128) {
        int gc = n0 + tid;
        sBias[tid] = (gc < biasN) ? bias[gc] : 0.0f;
    }

    float acc[4][4][4];
#pragma unroll
    for (int i = 0; i < 4; i++)
#pragma unroll
        for (int j = 0; j < 4; j++)
#pragma unroll
            for (int q = 0; q < 4; q++) acc[i][j][q] = 0.0f;

    const uint32_t asHi = s2u(sAhi), asLo = s2u(sAlo);
    const uint32_t bsHi = s2u(sBhi), bsLo = s2u(sBlo);
    const int aRow = wm * 64 + (lane & 15);
    const int aCol = ((lane >> 4) & 1) * 8;
    const int bRow = wn * 32 + (lane & 7) + ((lane & 16) ? 8 : 0);
    const int bCol = (lane & 8) ? 8 : 0;

#pragma unroll 1
    for (int kc = 0; kc < 4; kc++) {
        const int kbase = kc * 32;
        __syncthreads();
        // load 4 tiles: 128 rows x 2 16B-chunks each, 2 rows/thread
#pragma unroll
        for (int c = tid; c < 512; c += 256) {
            int r = c >> 2, ch = c & 3;
            int gm = m0 + r;
            uint4 vh = make_uint4(0, 0, 0, 0), vl = vh;
            if (gm < M) {
                vh = *(const uint4*)(&g_Ahi[(size_t)gm * 128 + kbase + ch * 8]);
                vl = *(const uint4*)(&g_Alo[(size_t)gm * 128 + kbase + ch * 8]);
            }
            *(uint4*)(&sAhi[r * TS + ch * 8]) = vh;
            *(uint4*)(&sAlo[r * TS + ch * 8]) = vl;
            int gn = n0 + r;  // B rows padded to tile grid; always valid
            *(uint4*)(&sBhi[r * TS + ch * 8]) =
                *(const uint4*)(&Bhi[(size_t)gn * 128 + kbase + ch * 8]);
            *(uint4*)(&sBlo[r * TS + ch * 8]) =
                *(const uint4*)(&Blo[(size_t)gn * 128 + kbase + ch * 8]);
        }
        __syncthreads();

#pragma unroll
        for (int pass = 0; pass < 3; pass++) {
            const uint32_t aB = (pass < 2) ? asHi : asLo;
            const uint32_t bB = (pass == 1) ? bsLo : bsHi;
#pragma unroll
            for (int ks = 0; ks < 2; ks++) {
                uint32_t bfr[4][2];
                {
                    uint32_t t[4];
                    ldm_x4(t, bB + (uint32_t)(bRow * TS + ks * 16 + bCol) * 2);
                    bfr[0][0] = t[0]; bfr[0][1] = t[1];
                    bfr[1][0] = t[2]; bfr[1][1] = t[3];
                    ldm_x4(t, bB + (uint32_t)((bRow + 16) * TS + ks * 16 + bCol) * 2);
                    bfr[2][0] = t[0]; bfr[2][1] = t[1];
                    bfr[3][0] = t[2]; bfr[3][1] = t[3];
                }
#pragma unroll
                for (int mt = 0; mt < 4; mt++) {
                    uint32_t afr[4];
                    ldm_x4(afr, aB + (uint32_t)((aRow + mt * 16) * TS + ks * 16 + aCol) * 2);
#pragma unroll
                    for (int nt = 0; nt < 4; nt++)
                        mma16816(acc[mt][nt], afr, bfr[nt]);
                }
            }
        }
    }

    __syncthreads();
    const int quad = lane >> 2, tq = lane & 3;
#pragma unroll
    for (int mt = 0; mt < 4; mt++) {
        int row = m0 + wm * 64 + mt * 16 + quad;
#pragma unroll
        for (int nt = 0; nt < 4; nt++) {
            int colL = wn * 32 + nt * 8 + tq * 2;
            int gc = n0 + colL;
            if (gc < Ncols) {
                float b0 = sBias[colL], b1 = sBias[colL + 1];
                if (row < M) {
                    float2 v0 = make_float2(acc[mt][nt][0] + b0, acc[mt][nt][1] + b1);
                    *(float2*)(&C[(size_t)row * Ncols + gc]) = v0;
                }
                if (row + 8 < M) {
                    float2 v1 = make_float2(acc[mt][nt][2] + b0, acc[mt][nt][3] + b1);
                    *(float2*)(&C[(size_t)(row + 8) * Ncols + gc]) = v1;
                }
            }
        }
    }
}

// ---------------- edge scatter, layer 1 (F=128, warp per sorted edge) --------
__global__ void k_scatter1(int E) {
    int w = (blockIdx.x * blockDim.x + threadIdx.x) >> 5;
    int lane = threadIdx.x & 31;
    if (w >= E) return;
    unsigned v = g_ega[w];
    int d = g_egd[w];
    float sc = g_esc[w];
    const float4* rp = (const float4*)(g_buf1 + (size_t)(v >> 3) * NC1 + F_HID
                                       + (size_t)(v & 7) * F_HID);
    float4 m = rp[lane];
    float* ap = g_buf1 + (size_t)d * NC1 + lane * 4;
    red4(ap, m.x * sc, m.y * sc, m.z * sc, m.w * sc);
}

// ---------------- edge scatter, layer 2 (F=64, half-warp per sorted edge) ----
__global__ void k_scatter2(int E) {
    int t = blockIdx.x * blockDim.x + threadIdx.x;
    int e = t >> 4, sub = t & 15;
    if (e >= E) return;
    unsigned v = g_ega[e];
    int d = g_egd[e];
    float sc = g_esc[e];
    const float4* rp = (const float4*)(g_buf1 + (size_t)(v >> 3) * NC2 + F_OUT
                                       + (size_t)(v & 7) * F_OUT);
    float4 m = rp[sub];
    float* ap = g_buf1 + (size_t)d * NC2 + sub * 4;
    red4(ap, m.x * sc, m.y * sc, m.z * sc, m.w * sc);
}

// ---------------- final copy --------------------------------------------------
__global__ void k_copy_out(float* __restrict__ out, int total) {  // total = N * F_OUT
    int i = blockIdx.x * blockDim.x + threadIdx.x;
    if (i >= total) return;
    int n = i >> 6, j = i & 63;
    out[i] = g_buf1[(size_t)n * NC2 + j];
}

// ---------------- launch -----------------------------------------------------
extern "C" void kernel_launch(void* const* d_in, const int* in_sizes, int n_in,
                              void* d_out, int out_size) {
    const float* x     = (const float*)d_in[0];
    const int*   ei    = (const int*)d_in[1];   // [2, E] int32 (JAX x64 disabled)
    const int*   et    = (const int*)d_in[2];   // [E]    int32
    const float* W1    = (const float*)d_in[3];
    const float* root1 = (const float*)d_in[4];
    const float* b1    = (const float*)d_in[5];
    const float* W2    = (const float*)d_in[6];
    const float* root2 = (const float*)d_in[7];
    const float* b2    = (const float*)d_in[8];
    float*       out   = (float*)d_out;

    const int N = in_sizes[0] / F_IN;
    const int E = in_sizes[2];
    const int* src = ei;
    const int* dst = ei + E;
    const int tilesM = (N + 127) / 128;

    // 1-3: prep for GEMM1 (so GEMM1 is the 4th launch -> ncu captures it)
    k_packB12<<<((NC1 + NPAD2) * 128 + 255) / 256, 256>>>(root1, W1, root2, W2);
    k_split_x<<<(N * F_IN + 255) / 256, 256>>>(x, N * F_IN);
    k_zero<<<(N * NREL + 255) / 256, 256>>>(N * NREL, N);

    // 4: layer-1 GEMM (captured by ncu -s 5 -c 1)
    {
        dim3 grid(NC1 / 128, tilesM);
        k_gemm_hmma<<<grid, 256>>>(1, b1, N, NC1, F_HID);
    }

    // 5-8: graph structure + edge sort (independent of GEMM1)
    k_count<<<(E + 255) / 256, 256>>>(src, dst, et, E);
    k_inv<<<(N * NREL + 255) / 256, 256>>>(N * NREL);
    k_scan<<<1, 1024>>>(N);
    k_fill<<<(E + 255) / 256, 256>>>(src, dst, et, E);

    // 9-10: scatter + relu/split
    k_scatter1<<<(E * 32 + 255) / 256, 256>>>(E);
    k_relu_split<<<(N * F_HID + 255) / 256, 256>>>(N * F_HID);

    // ---- layer 2 ----
    {
        dim3 grid(NPAD2 / 128, tilesM);
        k_gemm_hmma<<<grid, 256>>>(2, b2, N, NC2, F_OUT);
    }
    k_scatter2<<<(E * 16 + 255) / 256, 256>>>(E);
    k_copy_out<<<(N * F_OUT + 255) / 256, 256>>>(out, N * F_OUT);
}

// round 7
// speedup vs baseline: 2.2847x; 1.1678x over previous
#include <cuda_runtime.h>
#include <cuda_bf16.h>
#include <cstdint>

// Problem constants (fixed by the dataset).
#define NNODES   50000
#define NEDGES   800000
#define F_IN     128
#define F_HID    128
#define F_OUT    64
#define NREL     8
#define NC1      1152     // 128 root + 8*128 messages (layer 1 packed cols)
#define NC2      576      // 64 root + 8*64 (layer 2)
#define NPAD2    640      // NC2 padded to multiple of 128

// ---------------- scratch (static device globals; no allocation) -------------
__device__ __align__(128) float g_buf1[(size_t)NNODES * NC1];   // 230 MB, GEMM out + scatter acc
__device__ __align__(128) int   g_cnt [NNODES * NREL];          // per (dst,rel) counts
__device__ __align__(256) __nv_bfloat16 g_Ahi[(size_t)NNODES * 128];
__device__ __align__(256) __nv_bfloat16 g_Alo[(size_t)NNODES * 128];
__device__ __align__(256) __nv_bfloat16 g_B1hi[NC1 * 128];   // transposed Bt[n][k]
__device__ __align__(256) __nv_bfloat16 g_B1lo[NC1 * 128];
__device__ __align__(256) __nv_bfloat16 g_B2hi[NPAD2 * 128];
__device__ __align__(256) __nv_bfloat16 g_B2lo[NPAD2 * 128];
// edge CSR (by dst) structures
__device__ int      g_dcnt[NNODES];  // edges per dst
__device__ int      g_ptr [NNODES];  // fill cursor; after fill = row end
__device__ unsigned g_ega[NEDGES];   // src*8 + rel
__device__ float    g_esc[NEDGES];   // 1/max(cnt[dst,rel],1)

// ---------------- PTX helpers (plain sm_103-target ISA only) ------------------
__device__ __forceinline__ uint32_t s2u(const void* p) {
    return (uint32_t)__cvta_generic_to_shared(p);
}
__device__ __forceinline__ void ldm_x4(uint32_t* r, uint32_t addr) {
    asm volatile("ldmatrix.sync.aligned.m8n8.x4.shared.b16 {%0,%1,%2,%3}, [%4];"
                 : "=r"(r[0]), "=r"(r[1]), "=r"(r[2]), "=r"(r[3]) : "r"(addr));
}
__device__ __forceinline__ void mma16816(float* c, const uint32_t* a, const uint32_t* b) {
    asm volatile("mma.sync.aligned.m16n8k16.row.col.f32.bf16.bf16.f32 "
                 "{%0,%1,%2,%3}, {%4,%5,%6,%7}, {%8,%9}, {%0,%1,%2,%3};"
                 : "+f"(c[0]), "+f"(c[1]), "+f"(c[2]), "+f"(c[3])
                 : "r"(a[0]), "r"(a[1]), "r"(a[2]), "r"(a[3]), "r"(b[0]), "r"(b[1]));
}

// ---------------- weight packing (merged; transposed Bt[n][k], hi/lo split) ---
__global__ void k_packB12(const float* __restrict__ root1, const float* __restrict__ W1,
                          const float* __restrict__ root2, const float* __restrict__ W2) {
    int idx = blockIdx.x * blockDim.x + threadIdx.x;
    if (idx < NC1 * 128) {
        int n = idx >> 7, k = idx & 127;
        float v;
        if (n < F_HID) v = root1[k * F_HID + n];
        else {
            int r = (n - F_HID) >> 7, j = (n - F_HID) & 127;
            v = W1[((size_t)r * F_IN + k) * F_HID + j];
        }
        __nv_bfloat16 h = __float2bfloat16(v);
        g_B1hi[idx] = h;
        g_B1lo[idx] = __float2bfloat16(v - __bfloat162float(h));
    } else {
        int i2 = idx - NC1 * 128;
        if (i2 >= NPAD2 * 128) return;
        int n = i2 >> 7, k = i2 & 127;
        float v = 0.0f;
        if (n < NC2) {
            if (n < F_OUT) v = root2[k * F_OUT + n];
            else {
                int r = (n - F_OUT) >> 6, j = (n - F_OUT) & 63;
                v = W2[((size_t)r * F_HID + k) * F_OUT + j];
            }
        }
        __nv_bfloat16 h = __float2bfloat16(v);
        g_B2hi[i2] = h;
        g_B2lo[i2] = __float2bfloat16(v - __bfloat162float(h));
    }
}

// ---------------- bf16 hi/lo splits of activations ---------------------------
__global__ void k_split_x(const float* __restrict__ x, int total) {
    int i = blockIdx.x * blockDim.x + threadIdx.x;
    if (i >= total) return;
    float v = x[i];
    __nv_bfloat16 h = __float2bfloat16(v);
    g_Ahi[i] = h;
    g_Alo[i] = __float2bfloat16(v - __bfloat162float(h));
}
__global__ void k_relu_split(int total) {  // total = N * F_HID
    int i = blockIdx.x * blockDim.x + threadIdx.x;
    if (i >= total) return;
    int n = i >> 7, j = i & 127;
    float v = g_buf1[(size_t)n * NC1 + j];
    v = v > 0.0f ? v : 0.0f;
    __nv_bfloat16 h = __float2bfloat16(v);
    g_Ahi[i] = h;
    g_Alo[i] = __float2bfloat16(v - __bfloat162float(h));
}

// ---------------- graph-structure kernels ------------------------------------
__global__ void k_zero(int nA, int nB) {
    int i = blockIdx.x * blockDim.x + threadIdx.x;
    if (i < nA) g_cnt[i] = 0;
    if (i < nB) g_dcnt[i] = 0;
}
__global__ void k_count(const int* __restrict__ dst, const int* __restrict__ et, int E) {
    int e = blockIdx.x * blockDim.x + threadIdx.x;
    if (e >= E) return;
    int d = dst[e];
    atomicAdd(&g_cnt[d * NREL + et[e]], 1);
    atomicAdd(&g_dcnt[d], 1);
}
// single-block exclusive scan of g_dcnt -> g_ptr (n <= 50176)
__global__ void k_scan(int n) {
    __shared__ int part[1024];
    int t = threadIdx.x;
    const int CH = (n + 1023) / 1024;
    int base = t * CH;
    int s = 0;
    for (int i = 0; i < CH; i++) { int idx = base + i; if (idx < n) s += g_dcnt[idx]; }
    part[t] = s;
    __syncthreads();
    for (int off = 1; off < 1024; off <<= 1) {
        int v = (t >= off) ? part[t - off] : 0;
        __syncthreads();
        part[t] += v;
        __syncthreads();
    }
    int excl = (t == 0) ? 0 : part[t - 1];
    for (int i = 0; i < CH; i++) {
        int idx = base + i;
        if (idx < n) { g_ptr[idx] = excl; excl += g_dcnt[idx]; }
    }
}
__global__ void k_fill(const int* __restrict__ src, const int* __restrict__ dst,
                       const int* __restrict__ et, int E) {
    int e = blockIdx.x * blockDim.x + threadIdx.x;
    if (e >= E) return;
    int s = src[e], d = dst[e], r = et[e];
    int pos = atomicAdd(&g_ptr[d], 1);
    g_ega[pos] = (unsigned)(s * NREL + r);
    int c = g_cnt[d * NREL + r];
    g_esc[pos] = 1.0f / (float)(c > 1 ? c : 1);
}

// ---------------- bf16-split HMMA GEMM ---------------------------------------
// C[M, Ncols] = (Ahi+Alo)[M,128] @ (Bhi+Blo)t, + bias cols < biasN.
// Block 128x128, K chunked by 32; all 4 tiles resident. Fragment-level fusion:
// per (ks, mt) load ah/al once, bh/bl resident per ks; 3 mma chains share them.
// 8 warps: wm = w&1 (2 M-warps of 64), wn = w>>1 (4 N-warps of 32).
#define TS 40   // bf16 per SMEM row (32 data + 8 pad; conflict-free ldmatrix)

__global__ __launch_bounds__(256, 2)
void k_gemm_hmma(int b_sel, const float* __restrict__ bias,
                 int M, int Ncols, int biasN) {
    __shared__ __nv_bfloat16 sAhi[128 * TS], sAlo[128 * TS];
    __shared__ __nv_bfloat16 sBhi[128 * TS], sBlo[128 * TS];
    __shared__ float sBias[128];

    const __nv_bfloat16* Bhi = (b_sel == 1) ? &g_B1hi[0] : &g_B2hi[0];
    const __nv_bfloat16* Blo = (b_sel == 1) ? &g_B1lo[0] : &g_B2lo[0];
    float* C = &g_buf1[0];

    const int tid  = threadIdx.x;
    const int wid  = tid >> 5;
    const int lane = tid & 31;
    const int wm   = wid & 1;
    const int wn   = wid >> 1;
    const int n0 = blockIdx.x * 128;
    const int m0 = blockIdx.y * 128;

    if (tid < 128) {
        int gc = n0 + tid;
        sBias[tid] = (gc < biasN) ? bias[gc] : 0.0f;
    }

    float acc[4][4][4];
#pragma unroll
    for (int i = 0; i < 4; i++)
#pragma unroll
        for (int j = 0; j < 4; j++)
#pragma unroll
            for (int q = 0; q < 4; q++) acc[i][j][q] = 0.0f;

    const uint32_t asHi = s2u(sAhi), asLo = s2u(sAlo);
    const uint32_t bsHi = s2u(sBhi), bsLo = s2u(sBlo);
    const int aRow = wm * 64 + (lane & 15);
    const int aCol = ((lane >> 4) & 1) * 8;
    const int bRow = wn * 32 + (lane & 7) + ((lane & 16) ? 8 : 0);
    const int bCol = (lane & 8) ? 8 : 0;

#pragma unroll 1
    for (int kc = 0; kc < 4; kc++) {
        const int kbase = kc * 32;
        __syncthreads();
#pragma unroll
        for (int c = tid; c < 512; c += 256) {
            int r = c >> 2, ch = c & 3;
            int gm = m0 + r;
            uint4 vh = make_uint4(0, 0, 0, 0), vl = vh;
            if (gm < M) {
                vh = *(const uint4*)(&g_Ahi[(size_t)gm * 128 + kbase + ch * 8]);
                vl = *(const uint4*)(&g_Alo[(size_t)gm * 128 + kbase + ch * 8]);
            }
            *(uint4*)(&sAhi[r * TS + ch * 8]) = vh;
            *(uint4*)(&sAlo[r * TS + ch * 8]) = vl;
            int gn = n0 + r;  // B rows padded to tile grid; always valid
            *(uint4*)(&sBhi[r * TS + ch * 8]) =
                *(const uint4*)(&Bhi[(size_t)gn * 128 + kbase + ch * 8]);
            *(uint4*)(&sBlo[r * TS + ch * 8]) =
                *(const uint4*)(&Blo[(size_t)gn * 128 + kbase + ch * 8]);
        }
        __syncthreads();

#pragma unroll
        for (int ks = 0; ks < 2; ks++) {
            uint32_t bh[4][2], bl[4][2];
            {
                uint32_t t[4];
                ldm_x4(t, bsHi + (uint32_t)(bRow * TS + ks * 16 + bCol) * 2);
                bh[0][0] = t[0]; bh[0][1] = t[1]; bh[1][0] = t[2]; bh[1][1] = t[3];
                ldm_x4(t, bsHi + (uint32_t)((bRow + 16) * TS + ks * 16 + bCol) * 2);
                bh[2][0] = t[0]; bh[2][1] = t[1]; bh[3][0] = t[2]; bh[3][1] = t[3];
                ldm_x4(t, bsLo + (uint32_t)(bRow * TS + ks * 16 + bCol) * 2);
                bl[0][0] = t[0]; bl[0][1] = t[1]; bl[1][0] = t[2]; bl[1][1] = t[3];
                ldm_x4(t, bsLo + (uint32_t)((bRow + 16) * TS + ks * 16 + bCol) * 2);
                bl[2][0] = t[0]; bl[2][1] = t[1]; bl[3][0] = t[2]; bl[3][1] = t[3];
            }
#pragma unroll
            for (int mt = 0; mt < 4; mt++) {
                uint32_t ah[4], al[4];
                ldm_x4(ah, asHi + (uint32_t)((aRow + mt * 16) * TS + ks * 16 + aCol) * 2);
                ldm_x4(al, asLo + (uint32_t)((aRow + mt * 16) * TS + ks * 16 + aCol) * 2);
#pragma unroll
                for (int nt = 0; nt < 4; nt++) {
                    mma16816(acc[mt][nt], ah, bh[nt]);
                    mma16816(acc[mt][nt], ah, bl[nt]);
                    mma16816(acc[mt][nt], al, bh[nt]);
                }
            }
        }
    }

    __syncthreads();
    const int quad = lane >> 2, tq = lane & 3;
#pragma unroll
    for (int mt = 0; mt < 4; mt++) {
        int row = m0 + wm * 64 + mt * 16 + quad;
#pragma unroll
        for (int nt = 0; nt < 4; nt++) {
            int colL = wn * 32 + nt * 8 + tq * 2;
            int gc = n0 + colL;
            if (gc < Ncols) {
                float b0 = sBias[colL], b1 = sBias[colL + 1];
                if (row < M) {
                    float2 v0 = make_float2(acc[mt][nt][0] + b0, acc[mt][nt][1] + b1);
                    *(float2*)(&C[(size_t)row * Ncols + gc]) = v0;
                }
                if (row + 8 < M) {
                    float2 v1 = make_float2(acc[mt][nt][2] + b0, acc[mt][nt][3] + b1);
                    *(float2*)(&C[(size_t)(row + 8) * Ncols + gc]) = v1;
                }
            }
        }
    }
}

// ---------------- scatter, layer 1: warp owns one dst node (no atomics) ------
__global__ void k_scatter1(int N) {
    int d = (blockIdx.x * blockDim.x + threadIdx.x) >> 5;
    int lane = threadIdx.x & 31;
    if (d >= N) return;
    int end = g_ptr[d];
    int beg = end - g_dcnt[d];
    if (beg == end) return;
    float4 acc = make_float4(0.f, 0.f, 0.f, 0.f);
    for (int e = beg; e < end; e++) {
        unsigned v = g_ega[e];
        float sc = g_esc[e];
        const float4* rp = (const float4*)(g_buf1 + (size_t)(v >> 3) * NC1 + F_HID
                                           + (size_t)(v & 7) * F_HID);
        float4 m = rp[lane];
        acc.x += m.x * sc; acc.y += m.y * sc; acc.z += m.z * sc; acc.w += m.w * sc;
    }
    float4* ap = (float4*)(g_buf1 + (size_t)d * NC1) + lane;
    float4 cur = *ap;
    cur.x += acc.x; cur.y += acc.y; cur.z += acc.z; cur.w += acc.w;
    *ap = cur;
}

// ---------------- scatter, layer 2: warp owns one dst node, float2 lanes -----
__global__ void k_scatter2(int N) {
    int d = (blockIdx.x * blockDim.x + threadIdx.x) >> 5;
    int lane = threadIdx.x & 31;
    if (d >= N) return;
    int end = g_ptr[d];
    int beg = end - g_dcnt[d];
    if (beg == end) return;
    float2 acc = make_float2(0.f, 0.f);
    for (int e = beg; e < end; e++) {
        unsigned v = g_ega[e];
        float sc = g_esc[e];
        const float2* rp = (const float2*)(g_buf1 + (size_t)(v >> 3) * NC2 + F_OUT
                                           + (size_t)(v & 7) * F_OUT);
        float2 m = rp[lane];
        acc.x += m.x * sc; acc.y += m.y * sc;
    }
    float2* ap = (float2*)(g_buf1 + (size_t)d * NC2) + lane;
    float2 cur = *ap;
    cur.x += acc.x; cur.y += acc.y;
    *ap = cur;
}

// ---------------- final copy --------------------------------------------------
__global__ void k_copy_out(float* __restrict__ out, int total) {  // total = N * F_OUT
    int i = blockIdx.x * blockDim.x + threadIdx.x;
    if (i >= total) return;
    int n = i >> 6, j = i & 63;
    out[i] = g_buf1[(size_t)n * NC2 + j];
}

// ---------------- launch -----------------------------------------------------
extern "C" void kernel_launch(void* const* d_in, const int* in_sizes, int n_in,
                              void* d_out, int out_size) {
    const float* x     = (const float*)d_in[0];
    const int*   ei    = (const int*)d_in[1];   // [2, E] int32 (JAX x64 disabled)
    const int*   et    = (const int*)d_in[2];   // [E]    int32
    const float* W1    = (const float*)d_in[3];
    const float* root1 = (const float*)d_in[4];
    const float* b1    = (const float*)d_in[5];
    const float* W2    = (const float*)d_in[6];
    const float* root2 = (const float*)d_in[7];
    const float* b2    = (const float*)d_in[8];
    float*       out   = (float*)d_out;

    const int N = in_sizes[0] / F_IN;
    const int E = in_sizes[2];
    const int* src = ei;
    const int* dst = ei + E;
    const int tilesM = (N + 127) / 128;

    // 1-3: prep (GEMM1 stays the 4th launch -> ncu captures it)
    k_packB12<<<((NC1 + NPAD2) * 128 + 255) / 256, 256>>>(root1, W1, root2, W2);
    k_split_x<<<(N * F_IN + 255) / 256, 256>>>(x, N * F_IN);
    k_zero<<<(N * NREL + 255) / 256, 256>>>(N * NREL, N);

    // 4: layer-1 GEMM
    {
        dim3 grid(NC1 / 128, tilesM);
        k_gemm_hmma<<<grid, 256>>>(1, b1, N, NC1, F_HID);
    }

    // 5-7: CSR-by-dst edge sort (independent of GEMM1)
    k_count<<<(E + 255) / 256, 256>>>(dst, et, E);
    k_scan<<<1, 1024>>>(N);
    k_fill<<<(E + 255) / 256, 256>>>(src, dst, et, E);

    // 8-9: scatter + relu/split
    k_scatter1<<<(N * 32 + 255) / 256, 256>>>(N);
    k_relu_split<<<(N * F_HID + 255) / 256, 256>>>(N * F_HID);

    // ---- layer 2 ----
    {
        dim3 grid(NPAD2 / 128, tilesM);
        k_gemm_hmma<<<grid, 256>>>(2, b2, N, NC2, F_OUT);
    }
    k_scatter2<<<(N * 32 + 255) / 256, 256>>>(N);
    k_copy_out<<<(N * F_OUT + 255) / 256, 256>>>(out, N * F_OUT);
}

// round 8
// speedup vs baseline: 2.4671x; 1.0798x over previous
#include <cuda_runtime.h>
#include <cuda_bf16.h>
#include <cstdint>

// Problem constants (fixed by the dataset).
#define NNODES   50000
#define NEDGES   800000
#define F_IN     128
#define F_HID    128
#define F_OUT    64
#define NREL     8
#define NC1      1152     // 128 root + 8*128 messages (layer 1 packed cols)
#define NC2      576      // 64 root + 8*64 (layer 2)
#define NPAD2    640      // NC2 padded to multiple of 128

// ---------------- scratch (static device globals; no allocation) -------------
__device__ __align__(128) float g_buf1[(size_t)NNODES * NC1];   // 230 MB, GEMM out + scatter acc
__device__ __align__(128) int   g_cnt [NNODES * NREL];          // per (dst,rel) counts
__device__ __align__(256) __nv_bfloat16 g_Ahi[(size_t)NNODES * 128];
__device__ __align__(256) __nv_bfloat16 g_Alo[(size_t)NNODES * 128];
__device__ __align__(256) __nv_bfloat16 g_B1hi[NC1 * 128];   // transposed Bt[n][k]
__device__ __align__(256) __nv_bfloat16 g_B1lo[NC1 * 128];
__device__ __align__(256) __nv_bfloat16 g_B2hi[NPAD2 * 128];
__device__ __align__(256) __nv_bfloat16 g_B2lo[NPAD2 * 128];
// edge CSR (by dst) structures
__device__ int      g_dcnt[NNODES];  // edges per dst
__device__ int      g_ptr [NNODES];  // fill cursor; after fill = row end
__device__ unsigned g_ega[NEDGES];   // src*8 + rel
__device__ float    g_esc[NEDGES];   // 1/max(cnt[dst,rel],1)

// ---------------- PTX helpers (plain sm_103-target ISA only) ------------------
__device__ __forceinline__ uint32_t s2u(const void* p) {
    return (uint32_t)__cvta_generic_to_shared(p);
}
__device__ __forceinline__ void ldm_x4(uint32_t* r, uint32_t addr) {
    asm volatile("ldmatrix.sync.aligned.m8n8.x4.shared.b16 {%0,%1,%2,%3}, [%4];"
                 : "=r"(r[0]), "=r"(r[1]), "=r"(r[2]), "=r"(r[3]) : "r"(addr));
}
__device__ __forceinline__ void mma16816(float* c, const uint32_t* a, const uint32_t* b) {
    asm volatile("mma.sync.aligned.m16n8k16.row.col.f32.bf16.bf16.f32 "
                 "{%0,%1,%2,%3}, {%4,%5,%6,%7}, {%8,%9}, {%0,%1,%2,%3};"
                 : "+f"(c[0]), "+f"(c[1]), "+f"(c[2]), "+f"(c[3])
                 : "r"(a[0]), "r"(a[1]), "r"(a[2]), "r"(a[3]), "r"(b[0]), "r"(b[1]));
}
__device__ __forceinline__ void cpa16(uint32_t dst, const void* src, bool pred) {
    int sz = pred ? 16 : 0;
    asm volatile("cp.async.cg.shared.global [%0], [%1], 16, %2;"
                 :: "r"(dst), "l"(src), "r"(sz) : "memory");
}

// ---------------- weight packing (merged; transposed Bt[n][k], hi/lo split) ---
__global__ void k_packB12(const float* __restrict__ root1, const float* __restrict__ W1,
                          const float* __restrict__ root2, const float* __restrict__ W2) {
    int idx = blockIdx.x * blockDim.x + threadIdx.x;
    if (idx < NC1 * 128) {
        int n = idx >> 7, k = idx & 127;
        float v;
        if (n < F_HID) v = root1[k * F_HID + n];
        else {
            int r = (n - F_HID) >> 7, j = (n - F_HID) & 127;
            v = W1[((size_t)r * F_IN + k) * F_HID + j];
        }
        __nv_bfloat16 h = __float2bfloat16(v);
        g_B1hi[idx] = h;
        g_B1lo[idx] = __float2bfloat16(v - __bfloat162float(h));
    } else {
        int i2 = idx - NC1 * 128;
        if (i2 >= NPAD2 * 128) return;
        int n = i2 >> 7, k = i2 & 127;
        float v = 0.0f;
        if (n < NC2) {
            if (n < F_OUT) v = root2[k * F_OUT + n];
            else {
                int r = (n - F_OUT) >> 6, j = (n - F_OUT) & 63;
                v = W2[((size_t)r * F_HID + k) * F_OUT + j];
            }
        }
        __nv_bfloat16 h = __float2bfloat16(v);
        g_B2hi[i2] = h;
        g_B2lo[i2] = __float2bfloat16(v - __bfloat162float(h));
    }
}

// ---------------- bf16 hi/lo splits of activations ---------------------------
__global__ void k_split_x(const float* __restrict__ x, int total) {
    int i = blockIdx.x * blockDim.x + threadIdx.x;
    if (i >= total) return;
    float v = x[i];
    __nv_bfloat16 h = __float2bfloat16(v);
    g_Ahi[i] = h;
    g_Alo[i] = __float2bfloat16(v - __bfloat162float(h));
}
__global__ void k_relu_split(int total) {  // total = N * F_HID
    int i = blockIdx.x * blockDim.x + threadIdx.x;
    if (i >= total) return;
    int n = i >> 7, j = i & 127;
    float v = g_buf1[(size_t)n * NC1 + j];
    v = v > 0.0f ? v : 0.0f;
    __nv_bfloat16 h = __float2bfloat16(v);
    g_Ahi[i] = h;
    g_Alo[i] = __float2bfloat16(v - __bfloat162float(h));
}

// ---------------- graph-structure kernels ------------------------------------
__global__ void k_zero(int nA, int nB) {
    int i = blockIdx.x * blockDim.x + threadIdx.x;
    if (i < nA) g_cnt[i] = 0;
    if (i < nB) g_dcnt[i] = 0;
}
__global__ void k_count(const int* __restrict__ dst, const int* __restrict__ et, int E) {
    int e = blockIdx.x * blockDim.x + threadIdx.x;
    if (e >= E) return;
    int d = dst[e];
    atomicAdd(&g_cnt[d * NREL + et[e]], 1);
    atomicAdd(&g_dcnt[d], 1);
}
// single-block exclusive scan of g_dcnt -> g_ptr (n <= 50176)
__global__ void k_scan(int n) {
    __shared__ int part[1024];
    int t = threadIdx.x;
    const int CH = (n + 1023) / 1024;
    int base = t * CH;
    int s = 0;
    for (int i = 0; i < CH; i++) { int idx = base + i; if (idx < n) s += g_dcnt[idx]; }
    part[t] = s;
    __syncthreads();
    for (int off = 1; off < 1024; off <<= 1) {
        int v = (t >= off) ? part[t - off] : 0;
        __syncthreads();
        part[t] += v;
        __syncthreads();
    }
    int excl = (t == 0) ? 0 : part[t - 1];
    for (int i = 0; i < CH; i++) {
        int idx = base + i;
        if (idx < n) { g_ptr[idx] = excl; excl += g_dcnt[idx]; }
    }
}
__global__ void k_fill(const int* __restrict__ src, const int* __restrict__ dst,
                       const int* __restrict__ et, int E) {
    int e = blockIdx.x * blockDim.x + threadIdx.x;
    if (e >= E) return;
    int s = src[e], d = dst[e], r = et[e];
    int pos = atomicAdd(&g_ptr[d], 1);
    g_ega[pos] = (unsigned)(s * NREL + r);
    int c = g_cnt[d * NREL + r];
    g_esc[pos] = 1.0f / (float)(c > 1 ? c : 1);
}

// ---------------- bf16-split HMMA GEMM, cp.async 2-stage pipeline -------------
// C[M, Ncols] = (Ahi+Alo)[M,128] @ (Bhi+Blo)t, + bias cols < biasN.
// Block 128x128, K chunked by 32. 4 tiles (Ahi/Alo/Bhi/Blo) double-buffered in
// dynamic SMEM; chunk k+1 streams via cp.async while HMMA consumes chunk k.
// 8 warps: wm = w&1 (2 M-warps of 64), wn = w>>1 (4 N-warps of 32).
#define TS 40                 // bf16 per SMEM row (32 data + 8 pad)
#define TILE_B (128 * TS * 2) // 10240 bytes per tile
#define DSMEM  (2 * 4 * TILE_B)

__global__ __launch_bounds__(256, 2)
void k_gemm_hmma(int b_sel, const float* __restrict__ bias,
                 int M, int Ncols, int biasN) {
    extern __shared__ char dynsm[];
    __shared__ float sBias[128];

    const __nv_bfloat16* gBhi = (b_sel == 1) ? &g_B1hi[0] : &g_B2hi[0];
    const __nv_bfloat16* gBlo = (b_sel == 1) ? &g_B1lo[0] : &g_B2lo[0];
    float* C = &g_buf1[0];

    const int tid  = threadIdx.x;
    const int wid  = tid >> 5;
    const int lane = tid & 31;
    const int wm   = wid & 1;
    const int wn   = wid >> 1;
    const int n0 = blockIdx.x * 128;
    const int m0 = blockIdx.y * 128;

    const uint32_t smBase = s2u(dynsm);

    if (tid < 128) {
        int gc = n0 + tid;
        sBias[tid] = (gc < biasN) ? bias[gc] : 0.0f;
    }

    float acc[4][4][4];
#pragma unroll
    for (int i = 0; i < 4; i++)
#pragma unroll
        for (int j = 0; j < 4; j++)
#pragma unroll
            for (int q = 0; q < 4; q++) acc[i][j][q] = 0.0f;

    const int aRow = wm * 64 + (lane & 15);
    const int aCol = ((lane >> 4) & 1) * 8;
    const int bRow = wn * 32 + (lane & 7) + ((lane & 16) ? 8 : 0);
    const int bCol = (lane & 8) ? 8 : 0;

    // issue cp.async loads for K-chunk kc into stage st
    auto issue_chunk = [&](int kc, int st) {
        const int kbase = kc * 32;
        const uint32_t stBase = smBase + (uint32_t)(st * 4 * TILE_B);
#pragma unroll
        for (int c = tid; c < 512; c += 256) {
            int r = c >> 2, ch = c & 3;
            int gm = m0 + r;
            bool pa = gm < M;
            int gmc = pa ? gm : 0;
            int gn = n0 + r;  // B rows padded to tile grid; always valid
            uint32_t so = (uint32_t)(r * TS + ch * 8) * 2;
            cpa16(stBase + 0 * TILE_B + so, &g_Ahi[(size_t)gmc * 128 + kbase + ch * 8], pa);
            cpa16(stBase + 1 * TILE_B + so, &g_Alo[(size_t)gmc * 128 + kbase + ch * 8], pa);
            cpa16(stBase + 2 * TILE_B + so, &gBhi[(size_t)gn * 128 + kbase + ch * 8], true);
            cpa16(stBase + 3 * TILE_B + so, &gBlo[(size_t)gn * 128 + kbase + ch * 8], true);
        }
        asm volatile("cp.async.commit_group;" ::: "memory");
    };

    issue_chunk(0, 0);

#pragma unroll 1
    for (int kc = 0; kc < 4; kc++) {
        const int st = kc & 1;
        if (kc < 3) {
            issue_chunk(kc + 1, st ^ 1);
            asm volatile("cp.async.wait_group 1;" ::: "memory");
        } else {
            asm volatile("cp.async.wait_group 0;" ::: "memory");
        }
        __syncthreads();

        const uint32_t stBase = smBase + (uint32_t)(st * 4 * TILE_B);
        const uint32_t asHi = stBase, asLo = stBase + TILE_B;
        const uint32_t bsHi = stBase + 2 * TILE_B, bsLo = stBase + 3 * TILE_B;

#pragma unroll
        for (int ks = 0; ks < 2; ks++) {
            uint32_t bh[4][2], bl[4][2];
            {
                uint32_t t[4];
                ldm_x4(t, bsHi + (uint32_t)(bRow * TS + ks * 16 + bCol) * 2);
                bh[0][0] = t[0]; bh[0][1] = t[1]; bh[1][0] = t[2]; bh[1][1] = t[3];
                ldm_x4(t, bsHi + (uint32_t)((bRow + 16) * TS + ks * 16 + bCol) * 2);
                bh[2][0] = t[0]; bh[2][1] = t[1]; bh[3][0] = t[2]; bh[3][1] = t[3];
                ldm_x4(t, bsLo + (uint32_t)(bRow * TS + ks * 16 + bCol) * 2);
                bl[0][0] = t[0]; bl[0][1] = t[1]; bl[1][0] = t[2]; bl[1][1] = t[3];
                ldm_x4(t, bsLo + (uint32_t)((bRow + 16) * TS + ks * 16 + bCol) * 2);
                bl[2][0] = t[0]; bl[2][1] = t[1]; bl[3][0] = t[2]; bl[3][1] = t[3];
            }
#pragma unroll
            for (int mt = 0; mt < 4; mt++) {
                uint32_t ah[4], al[4];
                ldm_x4(ah, asHi + (uint32_t)((aRow + mt * 16) * TS + ks * 16 + aCol) * 2);
                ldm_x4(al, asLo + (uint32_t)((aRow + mt * 16) * TS + ks * 16 + aCol) * 2);
#pragma unroll
                for (int nt = 0; nt < 4; nt++) {
                    mma16816(acc[mt][nt], ah, bh[nt]);
                    mma16816(acc[mt][nt], ah, bl[nt]);
                    mma16816(acc[mt][nt], al, bh[nt]);
                }
            }
        }
        __syncthreads();
    }

    const int quad = lane >> 2, tq = lane & 3;
#pragma unroll
    for (int mt = 0; mt < 4; mt++) {
        int row = m0 + wm * 64 + mt * 16 + quad;
#pragma unroll
        for (int nt = 0; nt < 4; nt++) {
            int colL = wn * 32 + nt * 8 + tq * 2;
            int gc = n0 + colL;
            if (gc < Ncols) {
                float b0 = sBias[colL], b1 = sBias[colL + 1];
                if (row < M) {
                    float2 v0 = make_float2(acc[mt][nt][0] + b0, acc[mt][nt][1] + b1);
                    *(float2*)(&C[(size_t)row * Ncols + gc]) = v0;
                }
                if (row + 8 < M) {
                    float2 v1 = make_float2(acc[mt][nt][2] + b0, acc[mt][nt][3] + b1);
                    *(float2*)(&C[(size_t)(row + 8) * Ncols + gc]) = v1;
                }
            }
        }
    }
}

// ---------------- scatter, layer 1: warp owns one dst node (no atomics) ------
__global__ void k_scatter1(int N) {
    int d = (blockIdx.x * blockDim.x + threadIdx.x) >> 5;
    int lane = threadIdx.x & 31;
    if (d >= N) return;
    int end = g_ptr[d];
    int beg = end - g_dcnt[d];
    if (beg == end) return;
    float4 acc = make_float4(0.f, 0.f, 0.f, 0.f);
    int e = beg;
    for (; e + 1 < end; e += 2) {
        unsigned v0 = g_ega[e], v1 = g_ega[e + 1];
        float s0 = g_esc[e], s1 = g_esc[e + 1];
        const float4* r0 = (const float4*)(g_buf1 + (size_t)(v0 >> 3) * NC1 + F_HID
                                           + (size_t)(v0 & 7) * F_HID);
        const float4* r1 = (const float4*)(g_buf1 + (size_t)(v1 >> 3) * NC1 + F_HID
                                           + (size_t)(v1 & 7) * F_HID);
        float4 m0 = r0[lane];
        float4 m1 = r1[lane];
        acc.x += m0.x * s0; acc.y += m0.y * s0; acc.z += m0.z * s0; acc.w += m0.w * s0;
        acc.x += m1.x * s1; acc.y += m1.y * s1; acc.z += m1.z * s1; acc.w += m1.w * s1;
    }
    if (e < end) {
        unsigned v = g_ega[e];
        float sc = g_esc[e];
        const float4* rp = (const float4*)(g_buf1 + (size_t)(v >> 3) * NC1 + F_HID
                                           + (size_t)(v & 7) * F_HID);
        float4 m = rp[lane];
        acc.x += m.x * sc; acc.y += m.y * sc; acc.z += m.z * sc; acc.w += m.w * sc;
    }
    float4* ap = (float4*)(g_buf1 + (size_t)d * NC1) + lane;
    float4 cur = *ap;
    cur.x += acc.x; cur.y += acc.y; cur.z += acc.z; cur.w += acc.w;
    *ap = cur;
}

// ---------------- scatter, layer 2: warp owns one dst node, float2 lanes -----
__global__ void k_scatter2(int N) {
    int d = (blockIdx.x * blockDim.x + threadIdx.x) >> 5;
    int lane = threadIdx.x & 31;
    if (d >= N) return;
    int end = g_ptr[d];
    int beg = end - g_dcnt[d];
    if (beg == end) return;
    float2 acc = make_float2(0.f, 0.f);
    int e = beg;
    for (; e + 1 < end; e += 2) {
        unsigned v0 = g_ega[e], v1 = g_ega[e + 1];
        float s0 = g_esc[e], s1 = g_esc[e + 1];
        const float2* r0 = (const float2*)(g_buf1 + (size_t)(v0 >> 3) * NC2 + F_OUT
                                           + (size_t)(v0 & 7) * F_OUT);
        const float2* r1 = (const float2*)(g_buf1 + (size_t)(v1 >> 3) * NC2 + F_OUT
                                           + (size_t)(v1 & 7) * F_OUT);
        float2 m0 = r0[lane];
        float2 m1 = r1[lane];
        acc.x += m0.x * s0; acc.y += m0.y * s0;
        acc.x += m1.x * s1; acc.y += m1.y * s1;
    }
    if (e < end) {
        unsigned v = g_ega[e];
        float sc = g_esc[e];
        const float2* rp = (const float2*)(g_buf1 + (size_t)(v >> 3) * NC2 + F_OUT
                                           + (size_t)(v & 7) * F_OUT);
        float2 m = rp[lane];
        acc.x += m.x * sc; acc.y += m.y * sc;
    }
    float2* ap = (float2*)(g_buf1 + (size_t)d * NC2) + lane;
    float2 cur = *ap;
    cur.x += acc.x; cur.y += acc.y;
    *ap = cur;
}

// ---------------- final copy --------------------------------------------------
__global__ void k_copy_out(float* __restrict__ out, int total) {  // total = N * F_OUT
    int i = blockIdx.x * blockDim.x + threadIdx.x;
    if (i >= total) return;
    int n = i >> 6, j = i & 63;
    out[i] = g_buf1[(size_t)n * NC2 + j];
}

// ---------------- launch -----------------------------------------------------
extern "C" void kernel_launch(void* const* d_in, const int* in_sizes, int n_in,
                              void* d_out, int out_size) {
    const float* x     = (const float*)d_in[0];
    const int*   ei    = (const int*)d_in[1];   // [2, E] int32 (JAX x64 disabled)
    const int*   et    = (const int*)d_in[2];   // [E]    int32
    const float* W1    = (const float*)d_in[3];
    const float* root1 = (const float*)d_in[4];
    const float* b1    = (const float*)d_in[5];
    const float* W2    = (const float*)d_in[6];
    const float* root2 = (const float*)d_in[7];
    const float* b2    = (const float*)d_in[8];
    float*       out   = (float*)d_out;

    const int N = in_sizes[0] / F_IN;
    const int E = in_sizes[2];
    const int* src = ei;
    const int* dst = ei + E;
    const int tilesM = (N + 127) / 128;

    static bool attr_done = false;
    if (!attr_done) {
        cudaFuncSetAttribute(k_gemm_hmma, cudaFuncAttributeMaxDynamicSharedMemorySize, DSMEM);
        attr_done = true;
    }

    // 1-3: prep (GEMM1 stays the 4th launch -> ncu captures it)
    k_packB12<<<((NC1 + NPAD2) * 128 + 255) / 256, 256>>>(root1, W1, root2, W2);
    k_split_x<<<(N * F_IN + 255) / 256, 256>>>(x, N * F_IN);
    k_zero<<<(N * NREL + 255) / 256, 256>>>(N * NREL, N);

    // 4: layer-1 GEMM
    {
        dim3 grid(NC1 / 128, tilesM);
        k_gemm_hmma<<<grid, 256, DSMEM>>>(1, b1, N, NC1, F_HID);
    }

    // 5-7: CSR-by-dst edge sort (independent of GEMM1)
    k_count<<<(E + 255) / 256, 256>>>(dst, et, E);
    k_scan<<<1, 1024>>>(N);
    k_fill<<<(E + 255) / 256, 256>>>(src, dst, et, E);

    // 8-9: scatter + relu/split
    k_scatter1<<<(N * 32 + 255) / 256, 256>>>(N);
    k_relu_split<<<(N * F_HID + 255) / 256, 256>>>(N * F_HID);

    // ---- layer 2 ----
    {
        dim3 grid(NPAD2 / 128, tilesM);
        k_gemm_hmma<<<grid, 256, DSMEM>>>(2, b2, N, NC2, F_OUT);
    }
    k_scatter2<<<(N * 32 + 255) / 256, 256>>>(N);
    k_copy_out<<<(N * F_OUT + 255) / 256, 256>>>(out, N * F_OUT);
}

// round 9
// speedup vs baseline: 2.5129x; 1.0186x over previous
#include <cuda_runtime.h>
#include <cuda_bf16.h>
#include <cstdint>

// Problem constants (fixed by the dataset).
#define NNODES   50000
#define NEDGES   800000
#define F_IN     128
#define F_HID    128
#define F_OUT    64
#define NREL     8
#define NC1      1152     // 128 root + 8*128 messages (layer 1 packed cols)
#define NC2      576      // 64 root + 8*64 (layer 2)
#define NPAD2    640      // NC2 padded to multiple of 128

// ---------------- scratch (static device globals; no allocation) -------------
__device__ __align__(128) float g_buf1[(size_t)NNODES * NC1];   // 230 MB, GEMM out
__device__ __align__(256) __nv_bfloat16 g_Ahi[(size_t)NNODES * 128];
__device__ __align__(256) __nv_bfloat16 g_Alo[(size_t)NNODES * 128];
__device__ __align__(256) __nv_bfloat16 g_B1hi[NC1 * 128];   // transposed Bt[n][k]
__device__ __align__(256) __nv_bfloat16 g_B1lo[NC1 * 128];
__device__ __align__(256) __nv_bfloat16 g_B2hi[NPAD2 * 128];
__device__ __align__(256) __nv_bfloat16 g_B2lo[NPAD2 * 128];
// edge CSR (by dst) structures
__device__ int      g_dcnt[NNODES];  // edges per dst
__device__ int      g_ptr [NNODES];  // fill cursor; after fill = row end
__device__ unsigned g_ega[NEDGES];   // src*8 + rel

// ---------------- PTX helpers (plain sm_103-target ISA only) ------------------
__device__ __forceinline__ uint32_t s2u(const void* p) {
    return (uint32_t)__cvta_generic_to_shared(p);
}
__device__ __forceinline__ void ldm_x4(uint32_t* r, uint32_t addr) {
    asm volatile("ldmatrix.sync.aligned.m8n8.x4.shared.b16 {%0,%1,%2,%3}, [%4];"
                 : "=r"(r[0]), "=r"(r[1]), "=r"(r[2]), "=r"(r[3]) : "r"(addr));
}
__device__ __forceinline__ void mma16816(float* c, const uint32_t* a, const uint32_t* b) {
    asm volatile("mma.sync.aligned.m16n8k16.row.col.f32.bf16.bf16.f32 "
                 "{%0,%1,%2,%3}, {%4,%5,%6,%7}, {%8,%9}, {%0,%1,%2,%3};"
                 : "+f"(c[0]), "+f"(c[1]), "+f"(c[2]), "+f"(c[3])
                 : "r"(a[0]), "r"(a[1]), "r"(a[2]), "r"(a[3]), "r"(b[0]), "r"(b[1]));
}
__device__ __forceinline__ void cpa16(uint32_t dst, const void* src, bool pred) {
    int sz = pred ? 16 : 0;
    asm volatile("cp.async.cg.shared.global [%0], [%1], 16, %2;"
                 :: "r"(dst), "l"(src), "r"(sz) : "memory");
}
struct BF4 { __nv_bfloat162 a, b; };   // 8-byte packed store of 4 bf16

// ---------------- weight packing (merged; transposed Bt[n][k], hi/lo split) ---
__global__ void k_packB12(const float* __restrict__ root1, const float* __restrict__ W1,
                          const float* __restrict__ root2, const float* __restrict__ W2) {
    int idx = blockIdx.x * blockDim.x + threadIdx.x;
    if (idx < NC1 * 128) {
        int n = idx >> 7, k = idx & 127;
        float v;
        if (n < F_HID) v = root1[k * F_HID + n];
        else {
            int r = (n - F_HID) >> 7, j = (n - F_HID) & 127;
            v = W1[((size_t)r * F_IN + k) * F_HID + j];
        }
        __nv_bfloat16 h = __float2bfloat16(v);
        g_B1hi[idx] = h;
        g_B1lo[idx] = __float2bfloat16(v - __bfloat162float(h));
    } else {
        int i2 = idx - NC1 * 128;
        if (i2 >= NPAD2 * 128) return;
        int n = i2 >> 7, k = i2 & 127;
        float v = 0.0f;
        if (n < NC2) {
            if (n < F_OUT) v = root2[k * F_OUT + n];
            else {
                int r = (n - F_OUT) >> 6, j = (n - F_OUT) & 63;
                v = W2[((size_t)r * F_HID + k) * F_OUT + j];
            }
        }
        __nv_bfloat16 h = __float2bfloat16(v);
        g_B2hi[i2] = h;
        g_B2lo[i2] = __float2bfloat16(v - __bfloat162float(h));
    }
}

// ---------------- bf16 hi/lo split of input x --------------------------------
__global__ void k_split_x(const float* __restrict__ x, int total) {
    int i = blockIdx.x * blockDim.x + threadIdx.x;
    if (i >= total) return;
    float v = x[i];
    __nv_bfloat16 h = __float2bfloat16(v);
    g_Ahi[i] = h;
    g_Alo[i] = __float2bfloat16(v - __bfloat162float(h));
}

// ---------------- graph-structure kernels ------------------------------------
__global__ void k_zero(int n) {
    int i = blockIdx.x * blockDim.x + threadIdx.x;
    if (i < n) g_dcnt[i] = 0;
}
__global__ void k_count(const int* __restrict__ dst, int E) {
    int e = blockIdx.x * blockDim.x + threadIdx.x;
    if (e >= E) return;
    atomicAdd(&g_dcnt[dst[e]], 1);
}
// single-block exclusive scan of g_dcnt -> g_ptr (n <= 50176)
__global__ void k_scan(int n) {
    __shared__ int part[1024];
    int t = threadIdx.x;
    const int CH = (n + 1023) / 1024;
    int base = t * CH;
    int s = 0;
    for (int i = 0; i < CH; i++) { int idx = base + i; if (idx < n) s += g_dcnt[idx]; }
    part[t] = s;
    __syncthreads();
    for (int off = 1; off < 1024; off <<= 1) {
        int v = (t >= off) ? part[t - off] : 0;
        __syncthreads();
        part[t] += v;
        __syncthreads();
    }
    int excl = (t == 0) ? 0 : part[t - 1];
    for (int i = 0; i < CH; i++) {
        int idx = base + i;
        if (idx < n) { g_ptr[idx] = excl; excl += g_dcnt[idx]; }
    }
}
__global__ void k_fill(const int* __restrict__ src, const int* __restrict__ dst,
                       const int* __restrict__ et, int E) {
    int e = blockIdx.x * blockDim.x + threadIdx.x;
    if (e >= E) return;
    int pos = atomicAdd(&g_ptr[dst[e]], 1);
    g_ega[pos] = (unsigned)(src[e] * NREL + et[e]);
}

// ---------------- bf16-split HMMA GEMM, cp.async 2-stage pipeline -------------
#define TS 40                 // bf16 per SMEM row (32 data + 8 pad)
#define TILE_B (128 * TS * 2) // 10240 bytes per tile
#define DSMEM  (2 * 4 * TILE_B)

__global__ __launch_bounds__(256, 2)
void k_gemm_hmma(int b_sel, const float* __restrict__ bias,
                 int M, int Ncols, int biasN) {
    extern __shared__ char dynsm[];
    __shared__ float sBias[128];

    const __nv_bfloat16* gBhi = (b_sel == 1) ? &g_B1hi[0] : &g_B2hi[0];
    const __nv_bfloat16* gBlo = (b_sel == 1) ? &g_B1lo[0] : &g_B2lo[0];
    float* C = &g_buf1[0];

    const int tid  = threadIdx.x;
    const int wid  = tid >> 5;
    const int lane = tid & 31;
    const int wm   = wid & 1;
    const int wn   = wid >> 1;
    const int n0 = blockIdx.x * 128;
    const int m0 = blockIdx.y * 128;

    const uint32_t smBase = s2u(dynsm);

    if (tid < 128) {
        int gc = n0 + tid;
        sBias[tid] = (gc < biasN) ? bias[gc] : 0.0f;
    }

    float acc[4][4][4];
#pragma unroll
    for (int i = 0; i < 4; i++)
#pragma unroll
        for (int j = 0; j < 4; j++)
#pragma unroll
            for (int q = 0; q < 4; q++) acc[i][j][q] = 0.0f;

    const int aRow = wm * 64 + (lane & 15);
    const int aCol = ((lane >> 4) & 1) * 8;
    const int bRow = wn * 32 + (lane & 7) + ((lane & 16) ? 8 : 0);
    const int bCol = (lane & 8) ? 8 : 0;

    auto issue_chunk = [&](int kc, int st) {
        const int kbase = kc * 32;
        const uint32_t stBase = smBase + (uint32_t)(st * 4 * TILE_B);
#pragma unroll
        for (int c = tid; c < 512; c += 256) {
            int r = c >> 2, ch = c & 3;
            int gm = m0 + r;
            bool pa = gm < M;
            int gmc = pa ? gm : 0;
            int gn = n0 + r;  // B rows padded to tile grid; always valid
            uint32_t so = (uint32_t)(r * TS + ch * 8) * 2;
            cpa16(stBase + 0 * TILE_B + so, &g_Ahi[(size_t)gmc * 128 + kbase + ch * 8], pa);
            cpa16(stBase + 1 * TILE_B + so, &g_Alo[(size_t)gmc * 128 + kbase + ch * 8], pa);
            cpa16(stBase + 2 * TILE_B + so, &gBhi[(size_t)gn * 128 + kbase + ch * 8], true);
            cpa16(stBase + 3 * TILE_B + so, &gBlo[(size_t)gn * 128 + kbase + ch * 8], true);
        }
        asm volatile("cp.async.commit_group;" ::: "memory");
    };

    issue_chunk(0, 0);

#pragma unroll 1
    for (int kc = 0; kc < 4; kc++) {
        const int st = kc & 1;
        if (kc < 3) {
            issue_chunk(kc + 1, st ^ 1);
            asm volatile("cp.async.wait_group 1;" ::: "memory");
        } else {
            asm volatile("cp.async.wait_group 0;" ::: "memory");
        }
        __syncthreads();

        const uint32_t stBase = smBase + (uint32_t)(st * 4 * TILE_B);
        const uint32_t asHi = stBase, asLo = stBase + TILE_B;
        const uint32_t bsHi = stBase + 2 * TILE_B, bsLo = stBase + 3 * TILE_B;

#pragma unroll
        for (int ks = 0; ks < 2; ks++) {
            uint32_t bh[4][2], bl[4][2];
            {
                uint32_t t[4];
                ldm_x4(t, bsHi + (uint32_t)(bRow * TS + ks * 16 + bCol) * 2);
                bh[0][0] = t[0]; bh[0][1] = t[1]; bh[1][0] = t[2]; bh[1][1] = t[3];
                ldm_x4(t, bsHi + (uint32_t)((bRow + 16) * TS + ks * 16 + bCol) * 2);
                bh[2][0] = t[0]; bh[2][1] = t[1]; bh[3][0] = t[2]; bh[3][1] = t[3];
                ldm_x4(t, bsLo + (uint32_t)(bRow * TS + ks * 16 + bCol) * 2);
                bl[0][0] = t[0]; bl[0][1] = t[1]; bl[1][0] = t[2]; bl[1][1] = t[3];
                ldm_x4(t, bsLo + (uint32_t)((bRow + 16) * TS + ks * 16 + bCol) * 2);
                bl[2][0] = t[0]; bl[2][1] = t[1]; bl[3][0] = t[2]; bl[3][1] = t[3];
            }
#pragma unroll
            for (int mt = 0; mt < 4; mt++) {
                uint32_t ah[4], al[4];
                ldm_x4(ah, asHi + (uint32_t)((aRow + mt * 16) * TS + ks * 16 + aCol) * 2);
                ldm_x4(al, asLo + (uint32_t)((aRow + mt * 16) * TS + ks * 16 + aCol) * 2);
#pragma unroll
                for (int nt = 0; nt < 4; nt++) {
                    mma16816(acc[mt][nt], ah, bh[nt]);
                    mma16816(acc[mt][nt], ah, bl[nt]);
                    mma16816(acc[mt][nt], al, bh[nt]);
                }
            }
        }
        __syncthreads();
    }

    const int quad = lane >> 2, tq = lane & 3;
#pragma unroll
    for (int mt = 0; mt < 4; mt++) {
        int row = m0 + wm * 64 + mt * 16 + quad;
#pragma unroll
        for (int nt = 0; nt < 4; nt++) {
            int colL = wn * 32 + nt * 8 + tq * 2;
            int gc = n0 + colL;
            if (gc < Ncols) {
                float b0 = sBias[colL], b1 = sBias[colL + 1];
                if (row < M) {
                    float2 v0 = make_float2(acc[mt][nt][0] + b0, acc[mt][nt][1] + b1);
                    *(float2*)(&C[(size_t)row * Ncols + gc]) = v0;
                }
                if (row + 8 < M) {
                    float2 v1 = make_float2(acc[mt][nt][2] + b0, acc[mt][nt][3] + b1);
                    *(float2*)(&C[(size_t)(row + 8) * Ncols + gc]) = v1;
                }
            }
        }
    }
}

// ---------------- scatter1: warp owns dst; fused mean + relu + bf16 split -----
__global__ void k_scatter1(int N) {
    int d = (blockIdx.x * blockDim.x + threadIdx.x) >> 5;
    int lane = threadIdx.x & 31;
    if (d >= N) return;
    int end = g_ptr[d];
    int beg = end - g_dcnt[d];

    // phase 1: per-relation counts via ballots (warp-uniform results)
    int c0 = 0, c1 = 0, c2 = 0, c3 = 0, c4 = 0, c5 = 0, c6 = 0, c7 = 0;
    for (int base = beg; base < end; base += 32) {
        int e = base + lane;
        int r = (e < end) ? (int)(g_ega[e] & 7u) : -1;
        c0 += __popc(__ballot_sync(0xffffffffu, r == 0));
        c1 += __popc(__ballot_sync(0xffffffffu, r == 1));
        c2 += __popc(__ballot_sync(0xffffffffu, r == 2));
        c3 += __popc(__ballot_sync(0xffffffffu, r == 3));
        c4 += __popc(__ballot_sync(0xffffffffu, r == 4));
        c5 += __popc(__ballot_sync(0xffffffffu, r == 5));
        c6 += __popc(__ballot_sync(0xffffffffu, r == 6));
        c7 += __popc(__ballot_sync(0xffffffffu, r == 7));
    }
    int myc = (lane == 0) ? c0 : (lane == 1) ? c1 : (lane == 2) ? c2 : (lane == 3) ? c3
            : (lane == 4) ? c4 : (lane == 5) ? c5 : (lane == 6) ? c6 : (lane == 7) ? c7 : 1;
    float myinv = 1.0f / (float)(myc > 1 ? myc : 1);

    // phase 2: gather + accumulate (scale fetched via shfl from lane rel)
    float4 acc = make_float4(0.f, 0.f, 0.f, 0.f);
    for (int base = beg; base < end; base += 32) {
        int e = base + lane;
        unsigned vmine = (e < end) ? g_ega[e] : 0u;
        int nch = end - base; if (nch > 32) nch = 32;
        int j = 0;
        for (; j + 1 < nch; j += 2) {
            unsigned va = __shfl_sync(0xffffffffu, vmine, j);
            unsigned vb = __shfl_sync(0xffffffffu, vmine, j + 1);
            float sa = __shfl_sync(0xffffffffu, myinv, (int)(va & 7u));
            float sb = __shfl_sync(0xffffffffu, myinv, (int)(vb & 7u));
            const float4* ra = (const float4*)(g_buf1 + (size_t)(va >> 3) * NC1 + F_HID
                                               + (size_t)(va & 7u) * F_HID);
            const float4* rb = (const float4*)(g_buf1 + (size_t)(vb >> 3) * NC1 + F_HID
                                               + (size_t)(vb & 7u) * F_HID);
            float4 ma = ra[lane];
            float4 mb = rb[lane];
            acc.x += ma.x * sa; acc.y += ma.y * sa; acc.z += ma.z * sa; acc.w += ma.w * sa;
            acc.x += mb.x * sb; acc.y += mb.y * sb; acc.z += mb.z * sb; acc.w += mb.w * sb;
        }
        if (j < nch) {
            unsigned va = __shfl_sync(0xffffffffu, vmine, j);
            float sa = __shfl_sync(0xffffffffu, myinv, (int)(va & 7u));
            const float4* ra = (const float4*)(g_buf1 + (size_t)(va >> 3) * NC1 + F_HID
                                               + (size_t)(va & 7u) * F_HID);
            float4 ma = ra[lane];
            acc.x += ma.x * sa; acc.y += ma.y * sa; acc.z += ma.z * sa; acc.w += ma.w * sa;
        }
    }

    // fused epilogue: add root row, relu, bf16 hi/lo split -> g_Ahi/g_Alo
    float4 root = ((const float4*)(g_buf1 + (size_t)d * NC1))[lane];
    float f[4] = { root.x + acc.x, root.y + acc.y, root.z + acc.z, root.w + acc.w };
    __nv_bfloat16 hi[4], lo[4];
#pragma unroll
    for (int q = 0; q < 4; q++) {
        float v = f[q] > 0.0f ? f[q] : 0.0f;
        hi[q] = __float2bfloat16(v);
        lo[q] = __float2bfloat16(v - __bfloat162float(hi[q]));
    }
    BF4 wh, wl;
    wh.a = __halves2bfloat162(hi[0], hi[1]); wh.b = __halves2bfloat162(hi[2], hi[3]);
    wl.a = __halves2bfloat162(lo[0], lo[1]); wl.b = __halves2bfloat162(lo[2], lo[3]);
    *reinterpret_cast<BF4*>(&g_Ahi[(size_t)d * 128 + lane * 4]) = wh;
    *reinterpret_cast<BF4*>(&g_Alo[(size_t)d * 128 + lane * 4]) = wl;
}

// ---------------- scatter2: warp owns dst; fused mean + output write ----------
__global__ void k_scatter2(float* __restrict__ out, int N) {
    int d = (blockIdx.x * blockDim.x + threadIdx.x) >> 5;
    int lane = threadIdx.x & 31;
    if (d >= N) return;
    int end = g_ptr[d];
    int beg = end - g_dcnt[d];

    int c0 = 0, c1 = 0, c2 = 0, c3 = 0, c4 = 0, c5 = 0, c6 = 0, c7 = 0;
    for (int base = beg; base < end; base += 32) {
        int e = base + lane;
        int r = (e < end) ? (int)(g_ega[e] & 7u) : -1;
        c0 += __popc(__ballot_sync(0xffffffffu, r == 0));
        c1 += __popc(__ballot_sync(0xffffffffu, r == 1));
        c2 += __popc(__ballot_sync(0xffffffffu, r == 2));
        c3 += __popc(__ballot_sync(0xffffffffu, r == 3));
        c4 += __popc(__ballot_sync(0xffffffffu, r == 4));
        c5 += __popc(__ballot_sync(0xffffffffu, r == 5));
        c6 += __popc(__ballot_sync(0xffffffffu, r == 6));
        c7 += __popc(__ballot_sync(0xffffffffu, r == 7));
    }
    int myc = (lane == 0) ? c0 : (lane == 1) ? c1 : (lane == 2) ? c2 : (lane == 3) ? c3
            : (lane == 4) ? c4 : (lane == 5) ? c5 : (lane == 6) ? c6 : (lane == 7) ? c7 : 1;
    float myinv = 1.0f / (float)(myc > 1 ? myc : 1);

    float2 acc = make_float2(0.f, 0.f);
    for (int base = beg; base < end; base += 32) {
        int e = base + lane;
        unsigned vmine = (e < end) ? g_ega[e] : 0u;
        int nch = end - base; if (nch > 32) nch = 32;
        int j = 0;
        for (; j + 1 < nch; j += 2) {
            unsigned va = __shfl_sync(0xffffffffu, vmine, j);
            unsigned vb = __shfl_sync(0xffffffffu, vmine, j + 1);
            float sa = __shfl_sync(0xffffffffu, myinv, (int)(va & 7u));
            float sb = __shfl_sync(0xffffffffu, myinv, (int)(vb & 7u));
            const float2* ra = (const float2*)(g_buf1 + (size_t)(va >> 3) * NC2 + F_OUT
                                               + (size_t)(va & 7u) * F_OUT);
            const float2* rb = (const float2*)(g_buf1 + (size_t)(vb >> 3) * NC2 + F_OUT
                                               + (size_t)(vb & 7u) * F_OUT);
            float2 ma = ra[lane];
            float2 mb = rb[lane];
            acc.x += ma.x * sa; acc.y += ma.y * sa;
            acc.x += mb.x * sb; acc.y += mb.y * sb;
        }
        if (j < nch) {
            unsigned va = __shfl_sync(0xffffffffu, vmine, j);
            float sa = __shfl_sync(0xffffffffu, myinv, (int)(va & 7u));
            const float2* ra = (const float2*)(g_buf1 + (size_t)(va >> 3) * NC2 + F_OUT
                                               + (size_t)(va & 7u) * F_OUT);
            float2 ma = ra[lane];
            acc.x += ma.x * sa; acc.y += ma.y * sa;
        }
    }

    float2 root = ((const float2*)(g_buf1 + (size_t)d * NC2))[lane];
    float2 v = make_float2(root.x + acc.x, root.y + acc.y);
    *(float2*)(&out[(size_t)d * F_OUT + lane * 2]) = v;
}

// ---------------- launch -----------------------------------------------------
extern "C" void kernel_launch(void* const* d_in, const int* in_sizes, int n_in,
                              void* d_out, int out_size) {
    const float* x     = (const float*)d_in[0];
    const int*   ei    = (const int*)d_in[1];   // [2, E] int32 (JAX x64 disabled)
    const int*   et    = (const int*)d_in[2];   // [E]    int32
    const float* W1    = (const float*)d_in[3];
    const float* root1 = (const float*)d_in[4];
    const float* b1    = (const float*)d_in[5];
    const float* W2    = (const float*)d_in[6];
    const float* root2 = (const float*)d_in[7];
    const float* b2    = (const float*)d_in[8];
    float*       out   = (float*)d_out;

    const int N = in_sizes[0] / F_IN;
    const int E = in_sizes[2];
    const int* src = ei;
    const int* dst = ei + E;
    const int tilesM = (N + 127) / 128;

    static bool attr_done = false;
    if (!attr_done) {
        cudaFuncSetAttribute(k_gemm_hmma, cudaFuncAttributeMaxDynamicSharedMemorySize, DSMEM);
        attr_done = true;
    }

    // 1-3: prep (GEMM1 stays the 4th launch -> ncu captures it)
    k_packB12<<<((NC1 + NPAD2) * 128 + 255) / 256, 256>>>(root1, W1, root2, W2);
    k_split_x<<<(N * F_IN + 255) / 256, 256>>>(x, N * F_IN);
    k_zero<<<(N + 255) / 256, 256>>>(N);

    // 4: layer-1 GEMM
    {
        dim3 grid(NC1 / 128, tilesM);
        k_gemm_hmma<<<grid, 256, DSMEM>>>(1, b1, N, NC1, F_HID);
    }

    // 5-7: CSR-by-dst edge sort (independent of GEMM1)
    k_count<<<(E + 255) / 256, 256>>>(dst, E);
    k_scan<<<1, 1024>>>(N);
    k_fill<<<(E + 255) / 256, 256>>>(src, dst, et, E);

    // 8: scatter1 (fused mean + relu + split)
    k_scatter1<<<(N * 32 + 255) / 256, 256>>>(N);

    // 9: layer-2 GEMM
    {
        dim3 grid(NPAD2 / 128, tilesM);
        k_gemm_hmma<<<grid, 256, DSMEM>>>(2, b2, N, NC2, F_OUT);
    }

    // 10: scatter2 (fused mean + final output write)
    k_scatter2<<<(N * 32 + 255) / 256, 256>>>(out, N);
}

// round 10
// speedup vs baseline: 2.7464x; 1.0929x over previous
#include <cuda_runtime.h>
#include <cuda_bf16.h>
#include <cuda_fp16.h>
#include <cstdint>

// Problem constants (fixed by the dataset).
#define NNODES   50000
#define NEDGES   800000
#define F_IN     128
#define F_HID    128
#define F_OUT    64
#define NREL     8
#define NC1      1152     // 128 root + 8*128 messages (layer 1 packed cols)
#define NC2      576      // 64 root + 8*64 (layer 2)
#define NPAD2    640      // NC2 padded to multiple of 128

// ---------------- scratch (static device globals; no allocation) -------------
__device__ __align__(128) float  g_root1[(size_t)NNODES * 128];   // 25.6 MB fp32
__device__ __align__(128) __half g_msg1 [(size_t)NNODES * 1024];  // 102.4 MB fp16
__device__ __align__(128) float  g_root2[(size_t)NNODES * 64];    // 12.8 MB fp32
__device__ __align__(128) __half g_msg2 [(size_t)NNODES * 512];   // 51.2 MB fp16
__device__ __align__(256) __nv_bfloat16 g_Ahi[(size_t)NNODES * 128];
__device__ __align__(256) __nv_bfloat16 g_Alo[(size_t)NNODES * 128];
__device__ __align__(256) __nv_bfloat16 g_B1hi[NC1 * 128];   // transposed Bt[n][k]
__device__ __align__(256) __nv_bfloat16 g_B1lo[NC1 * 128];
__device__ __align__(256) __nv_bfloat16 g_B2hi[NPAD2 * 128];
__device__ __align__(256) __nv_bfloat16 g_B2lo[NPAD2 * 128];
// edge CSR (by dst) structures
__device__ int      g_dcnt[NNODES];  // edges per dst
__device__ int      g_ptr [NNODES];  // fill cursor; after fill = row end
__device__ unsigned g_ega[NEDGES];   // src*8 + rel

// ---------------- PTX helpers (plain sm_103-target ISA only) ------------------
__device__ __forceinline__ uint32_t s2u(const void* p) {
    return (uint32_t)__cvta_generic_to_shared(p);
}
__device__ __forceinline__ void ldm_x4(uint32_t* r, uint32_t addr) {
    asm volatile("ldmatrix.sync.aligned.m8n8.x4.shared.b16 {%0,%1,%2,%3}, [%4];"
                 : "=r"(r[0]), "=r"(r[1]), "=r"(r[2]), "=r"(r[3]) : "r"(addr));
}
__device__ __forceinline__ void mma16816(float* c, const uint32_t* a, const uint32_t* b) {
    asm volatile("mma.sync.aligned.m16n8k16.row.col.f32.bf16.bf16.f32 "
                 "{%0,%1,%2,%3}, {%4,%5,%6,%7}, {%8,%9}, {%0,%1,%2,%3};"
                 : "+f"(c[0]), "+f"(c[1]), "+f"(c[2]), "+f"(c[3])
                 : "r"(a[0]), "r"(a[1]), "r"(a[2]), "r"(a[3]), "r"(b[0]), "r"(b[1]));
}
__device__ __forceinline__ void cpa16(uint32_t dst, const void* src, bool pred) {
    int sz = pred ? 16 : 0;
    asm volatile("cp.async.cg.shared.global [%0], [%1], 16, %2;"
                 :: "r"(dst), "l"(src), "r"(sz) : "memory");
}
struct BF4 { __nv_bfloat162 a, b; };   // 8-byte packed store of 4 bf16

// fp16 message-row gather helpers
__device__ __forceinline__ void gacc1(unsigned v, float s, int lane, float4& acc) {
    const __half* bp = &g_msg1[(size_t)(v >> 3) * 1024 + (size_t)(v & 7u) * 128];
    uint2 u = *(const uint2*)(bp + lane * 4);
    __half2 h0 = *reinterpret_cast<__half2*>(&u.x);
    __half2 h1 = *reinterpret_cast<__half2*>(&u.y);
    float2 f0 = __half22float2(h0), f1 = __half22float2(h1);
    acc.x += f0.x * s; acc.y += f0.y * s; acc.z += f1.x * s; acc.w += f1.y * s;
}
__device__ __forceinline__ void gacc2(unsigned v, float s, int lane, float2& acc) {
    const __half* bp = &g_msg2[(size_t)(v >> 3) * 512 + (size_t)(v & 7u) * 64];
    __half2 h = *(const __half2*)(bp + lane * 2);
    float2 f = __half22float2(h);
    acc.x += f.x * s; acc.y += f.y * s;
}

// ---------------- combo prep: split_x + packB1 + packB2 + zero dcnt -----------
__global__ void k_combo(const float* __restrict__ x,
                        const float* __restrict__ root1, const float* __restrict__ W1,
                        const float* __restrict__ root2, const float* __restrict__ W2,
                        int N) {
    int i = blockIdx.x * blockDim.x + threadIdx.x;
    int splitTot = N * 128;
    if (i < splitTot) {
        float v = x[i];
        __nv_bfloat16 h = __float2bfloat16(v);
        g_Ahi[i] = h;
        g_Alo[i] = __float2bfloat16(v - __bfloat162float(h));
        return;
    }
    int j = i - splitTot;
    if (j < NC1 * 128) {
        int n = j >> 7, k = j & 127;
        float v;
        if (n < F_HID) v = root1[k * F_HID + n];
        else {
            int r = (n - F_HID) >> 7, jj = (n - F_HID) & 127;
            v = W1[((size_t)r * F_IN + k) * F_HID + jj];
        }
        __nv_bfloat16 h = __float2bfloat16(v);
        g_B1hi[j] = h;
        g_B1lo[j] = __float2bfloat16(v - __bfloat162float(h));
        return;
    }
    int j2 = j - NC1 * 128;
    if (j2 < NPAD2 * 128) {
        int n = j2 >> 7, k = j2 & 127;
        float v = 0.0f;
        if (n < NC2) {
            if (n < F_OUT) v = root2[k * F_OUT + n];
            else {
                int r = (n - F_OUT) >> 6, jj = (n - F_OUT) & 63;
                v = W2[((size_t)r * F_HID + k) * F_OUT + jj];
            }
        }
        __nv_bfloat16 h = __float2bfloat16(v);
        g_B2hi[j2] = h;
        g_B2lo[j2] = __float2bfloat16(v - __bfloat162float(h));
        return;
    }
    int j3 = j2 - NPAD2 * 128;
    if (j3 < N) g_dcnt[j3] = 0;
}

// ---------------- graph-structure kernels ------------------------------------
__global__ void k_count(const int* __restrict__ dst, int E) {
    int e = blockIdx.x * blockDim.x + threadIdx.x;
    if (e >= E) return;
    atomicAdd(&g_dcnt[dst[e]], 1);
}
// single-block exclusive scan of g_dcnt -> g_ptr (n <= 50176)
__global__ void k_scan(int n) {
    __shared__ int part[1024];
    int t = threadIdx.x;
    const int CH = (n + 1023) / 1024;
    int base = t * CH;
    int s = 0;
    for (int i = 0; i < CH; i++) { int idx = base + i; if (idx < n) s += g_dcnt[idx]; }
    part[t] = s;
    __syncthreads();
    for (int off = 1; off < 1024; off <<= 1) {
        int v = (t >= off) ? part[t - off] : 0;
        __syncthreads();
        part[t] += v;
        __syncthreads();
    }
    int excl = (t == 0) ? 0 : part[t - 1];
    for (int i = 0; i < CH; i++) {
        int idx = base + i;
        if (idx < n) { g_ptr[idx] = excl; excl += g_dcnt[idx]; }
    }
}
__global__ void k_fill(const int* __restrict__ src, const int* __restrict__ dst,
                       const int* __restrict__ et, int E) {
    int e = blockIdx.x * blockDim.x + threadIdx.x;
    if (e >= E) return;
    int pos = atomicAdd(&g_ptr[dst[e]], 1);
    g_ega[pos] = (unsigned)(src[e] * NREL + et[e]);
}

// ---------------- bf16-split HMMA GEMM, cp.async 2-stage pipeline -------------
#define TS 40                 // bf16 per SMEM row (32 data + 8 pad)
#define TILE_B (128 * TS * 2) // 10240 bytes per tile
#define DSMEM  (2 * 4 * TILE_B)

__global__ __launch_bounds__(256, 2)
void k_gemm_hmma(int b_sel, const float* __restrict__ bias,
                 int M, int biasN) {
    extern __shared__ char dynsm[];
    __shared__ float sBias[128];

    const __nv_bfloat16* gBhi = (b_sel == 1) ? &g_B1hi[0] : &g_B2hi[0];
    const __nv_bfloat16* gBlo = (b_sel == 1) ? &g_B1lo[0] : &g_B2lo[0];

    const int tid  = threadIdx.x;
    const int wid  = tid >> 5;
    const int lane = tid & 31;
    const int wm   = wid & 1;
    const int wn   = wid >> 1;
    const int n0 = blockIdx.x * 128;
    const int m0 = blockIdx.y * 128;

    const uint32_t smBase = s2u(dynsm);

    if (tid < 128) {
        int gc = n0 + tid;
        sBias[tid] = (gc < biasN) ? bias[gc] : 0.0f;
    }

    float acc[4][4][4];
#pragma unroll
    for (int i = 0; i < 4; i++)
#pragma unroll
        for (int j = 0; j < 4; j++)
#pragma unroll
            for (int q = 0; q < 4; q++) acc[i][j][q] = 0.0f;

    const int aRow = wm * 64 + (lane & 15);
    const int aCol = ((lane >> 4) & 1) * 8;
    const int bRow = wn * 32 + (lane & 7) + ((lane & 16) ? 8 : 0);
    const int bCol = (lane & 8) ? 8 : 0;

    auto issue_chunk = [&](int kc, int st) {
        const int kbase = kc * 32;
        const uint32_t stBase = smBase + (uint32_t)(st * 4 * TILE_B);
#pragma unroll
        for (int c = tid; c < 512; c += 256) {
            int r = c >> 2, ch = c & 3;
            int gm = m0 + r;
            bool pa = gm < M;
            int gmc = pa ? gm : 0;
            int gn = n0 + r;  // B rows padded to tile grid; always valid
            uint32_t so = (uint32_t)(r * TS + ch * 8) * 2;
            cpa16(stBase + 0 * TILE_B + so, &g_Ahi[(size_t)gmc * 128 + kbase + ch * 8], pa);
            cpa16(stBase + 1 * TILE_B + so, &g_Alo[(size_t)gmc * 128 + kbase + ch * 8], pa);
            cpa16(stBase + 2 * TILE_B + so, &gBhi[(size_t)gn * 128 + kbase + ch * 8], true);
            cpa16(stBase + 3 * TILE_B + so, &gBlo[(size_t)gn * 128 + kbase + ch * 8], true);
        }
        asm volatile("cp.async.commit_group;" ::: "memory");
    };

    issue_chunk(0, 0);

#pragma unroll 1
    for (int kc = 0; kc < 4; kc++) {
        const int st = kc & 1;
        if (kc < 3) {
            issue_chunk(kc + 1, st ^ 1);
            asm volatile("cp.async.wait_group 1;" ::: "memory");
        } else {
            asm volatile("cp.async.wait_group 0;" ::: "memory");
        }
        __syncthreads();

        const uint32_t stBase = smBase + (uint32_t)(st * 4 * TILE_B);
        const uint32_t asHi = stBase, asLo = stBase + TILE_B;
        const uint32_t bsHi = stBase + 2 * TILE_B, bsLo = stBase + 3 * TILE_B;

#pragma unroll
        for (int ks = 0; ks < 2; ks++) {
            uint32_t bh[4][2], bl[4][2];
            {
                uint32_t t[4];
                ldm_x4(t, bsHi + (uint32_t)(bRow * TS + ks * 16 + bCol) * 2);
                bh[0][0] = t[0]; bh[0][1] = t[1]; bh[1][0] = t[2]; bh[1][1] = t[3];
                ldm_x4(t, bsHi + (uint32_t)((bRow + 16) * TS + ks * 16 + bCol) * 2);
                bh[2][0] = t[0]; bh[2][1] = t[1]; bh[3][0] = t[2]; bh[3][1] = t[3];
                ldm_x4(t, bsLo + (uint32_t)(bRow * TS + ks * 16 + bCol) * 2);
                bl[0][0] = t[0]; bl[0][1] = t[1]; bl[1][0] = t[2]; bl[1][1] = t[3];
                ldm_x4(t, bsLo + (uint32_t)((bRow + 16) * TS + ks * 16 + bCol) * 2);
                bl[2][0] = t[0]; bl[2][1] = t[1]; bl[3][0] = t[2]; bl[3][1] = t[3];
            }
#pragma unroll
            for (int mt = 0; mt < 4; mt++) {
                uint32_t ah[4], al[4];
                ldm_x4(ah, asHi + (uint32_t)((aRow + mt * 16) * TS + ks * 16 + aCol) * 2);
                ldm_x4(al, asLo + (uint32_t)((aRow + mt * 16) * TS + ks * 16 + aCol) * 2);
#pragma unroll
                for (int nt = 0; nt < 4; nt++) {
                    mma16816(acc[mt][nt], ah, bh[nt]);
                    mma16816(acc[mt][nt], ah, bl[nt]);
                    mma16816(acc[mt][nt], al, bh[nt]);
                }
            }
        }
        __syncthreads();
    }

    // epilogue: root cols -> fp32 buffers, message cols -> fp16 buffers
    const int quad = lane >> 2, tq = lane & 3;
#pragma unroll
    for (int mt = 0; mt < 4; mt++) {
        int row = m0 + wm * 64 + mt * 16 + quad;
#pragma unroll
        for (int nt = 0; nt < 4; nt++) {
            int colL = wn * 32 + nt * 8 + tq * 2;
            int gc = n0 + colL;
            float b0 = sBias[colL], b1v = sBias[colL + 1];
            float2 v0 = make_float2(acc[mt][nt][0] + b0, acc[mt][nt][1] + b1v);
            float2 v1 = make_float2(acc[mt][nt][2] + b0, acc[mt][nt][3] + b1v);
            if (b_sel == 1) {
                if (n0 == 0) {
                    if (row < M)     *(float2*)&g_root1[(size_t)row * 128 + gc] = v0;
                    if (row + 8 < M) *(float2*)&g_root1[(size_t)(row + 8) * 128 + gc] = v1;
                } else {
                    int mc = gc - 128;
                    if (row < M)
                        *(__half2*)&g_msg1[(size_t)row * 1024 + mc] = __floats2half2_rn(v0.x, v0.y);
                    if (row + 8 < M)
                        *(__half2*)&g_msg1[(size_t)(row + 8) * 1024 + mc] = __floats2half2_rn(v1.x, v1.y);
                }
            } else {
                if (gc < 64) {
                    if (row < M)     *(float2*)&g_root2[(size_t)row * 64 + gc] = v0;
                    if (row + 8 < M) *(float2*)&g_root2[(size_t)(row + 8) * 64 + gc] = v1;
                } else if (gc < NC2) {
                    int mc = gc - 64;
                    if (row < M)
                        *(__half2*)&g_msg2[(size_t)row * 512 + mc] = __floats2half2_rn(v0.x, v0.y);
                    if (row + 8 < M)
                        *(__half2*)&g_msg2[(size_t)(row + 8) * 512 + mc] = __floats2half2_rn(v1.x, v1.y);
                }
            }
        }
    }
}

// ---------------- scatter1: warp owns dst; fused mean + relu + bf16 split -----
__global__ void k_scatter1(int N) {
    int d = (blockIdx.x * blockDim.x + threadIdx.x) >> 5;
    int lane = threadIdx.x & 31;
    if (d >= N) return;
    int end = g_ptr[d];
    int beg = end - g_dcnt[d];

    // per-relation counts via ballots (warp-uniform)
    int c0 = 0, c1 = 0, c2 = 0, c3 = 0, c4 = 0, c5 = 0, c6 = 0, c7 = 0;
    for (int base = beg; base < end; base += 32) {
        int e = base + lane;
        int r = (e < end) ? (int)(g_ega[e] & 7u) : -1;
        c0 += __popc(__ballot_sync(0xffffffffu, r == 0));
        c1 += __popc(__ballot_sync(0xffffffffu, r == 1));
        c2 += __popc(__ballot_sync(0xffffffffu, r == 2));
        c3 += __popc(__ballot_sync(0xffffffffu, r == 3));
        c4 += __popc(__ballot_sync(0xffffffffu, r == 4));
        c5 += __popc(__ballot_sync(0xffffffffu, r == 5));
        c6 += __popc(__ballot_sync(0xffffffffu, r == 6));
        c7 += __popc(__ballot_sync(0xffffffffu, r == 7));
    }
    int myc = (lane == 0) ? c0 : (lane == 1) ? c1 : (lane == 2) ? c2 : (lane == 3) ? c3
            : (lane == 4) ? c4 : (lane == 5) ? c5 : (lane == 6) ? c6 : (lane == 7) ? c7 : 1;
    float myinv = 1.0f / (float)(myc > 1 ? myc : 1);

    // gather + accumulate (4-way unroll; scale via shfl from lane rel)
    float4 acc = make_float4(0.f, 0.f, 0.f, 0.f);
    for (int base = beg; base < end; base += 32) {
        int e = base + lane;
        unsigned vmine = (e < end) ? g_ega[e] : 0u;
        int nch = end - base; if (nch > 32) nch = 32;
        int j = 0;
        for (; j + 3 < nch; j += 4) {
            unsigned va = __shfl_sync(0xffffffffu, vmine, j);
            unsigned vb = __shfl_sync(0xffffffffu, vmine, j + 1);
            unsigned vc = __shfl_sync(0xffffffffu, vmine, j + 2);
            unsigned vd = __shfl_sync(0xffffffffu, vmine, j + 3);
            float sa = __shfl_sync(0xffffffffu, myinv, (int)(va & 7u));
            float sb = __shfl_sync(0xffffffffu, myinv, (int)(vb & 7u));
            float sc = __shfl_sync(0xffffffffu, myinv, (int)(vc & 7u));
            float sd = __shfl_sync(0xffffffffu, myinv, (int)(vd & 7u));
            gacc1(va, sa, lane, acc);
            gacc1(vb, sb, lane, acc);
            gacc1(vc, sc, lane, acc);
            gacc1(vd, sd, lane, acc);
        }
        for (; j < nch; j++) {
            unsigned va = __shfl_sync(0xffffffffu, vmine, j);
            float sa = __shfl_sync(0xffffffffu, myinv, (int)(va & 7u));
            gacc1(va, sa, lane, acc);
        }
    }

    // fused epilogue: add root row, relu, bf16 hi/lo split -> g_Ahi/g_Alo
    float4 root = ((const float4*)&g_root1[(size_t)d * 128])[lane];
    float f[4] = { root.x + acc.x, root.y + acc.y, root.z + acc.z, root.w + acc.w };
    __nv_bfloat16 hi[4], lo[4];
#pragma unroll
    for (int q = 0; q < 4; q++) {
        float v = f[q] > 0.0f ? f[q] : 0.0f;
        hi[q] = __float2bfloat16(v);
        lo[q] = __float2bfloat16(v - __bfloat162float(hi[q]));
    }
    BF4 wh, wl;
    wh.a = __halves2bfloat162(hi[0], hi[1]); wh.b = __halves2bfloat162(hi[2], hi[3]);
    wl.a = __halves2bfloat162(lo[0], lo[1]); wl.b = __halves2bfloat162(lo[2], lo[3]);
    *reinterpret_cast<BF4*>(&g_Ahi[(size_t)d * 128 + lane * 4]) = wh;
    *reinterpret_cast<BF4*>(&g_Alo[(size_t)d * 128 + lane * 4]) = wl;
}

// ---------------- scatter2: warp owns dst; fused mean + output write ----------
__global__ void k_scatter2(float* __restrict__ out, int N) {
    int d = (blockIdx.x * blockDim.x + threadIdx.x) >> 5;
    int lane = threadIdx.x & 31;
    if (d >= N) return;
    int end = g_ptr[d];
    int beg = end - g_dcnt[d];

    int c0 = 0, c1 = 0, c2 = 0, c3 = 0, c4 = 0, c5 = 0, c6 = 0, c7 = 0;
    for (int base = beg; base < end; base += 32) {
        int e = base + lane;
        int r = (e < end) ? (int)(g_ega[e] & 7u) : -1;
        c0 += __popc(__ballot_sync(0xffffffffu, r == 0));
        c1 += __popc(__ballot_sync(0xffffffffu, r == 1));
        c2 += __popc(__ballot_sync(0xffffffffu, r == 2));
        c3 += __popc(__ballot_sync(0xffffffffu, r == 3));
        c4 += __popc(__ballot_sync(0xffffffffu, r == 4));
        c5 += __popc(__ballot_sync(0xffffffffu, r == 5));
        c6 += __popc(__ballot_sync(0xffffffffu, r == 6));
        c7 += __popc(__ballot_sync(0xffffffffu, r == 7));
    }
    int myc = (lane == 0) ? c0 : (lane == 1) ? c1 : (lane == 2) ? c2 : (lane == 3) ? c3
            : (lane == 4) ? c4 : (lane == 5) ? c5 : (lane == 6) ? c6 : (lane == 7) ? c7 : 1;
    float myinv = 1.0f / (float)(myc > 1 ? myc : 1);

    float2 acc = make_float2(0.f, 0.f);
    for (int base = beg; base < end; base += 32) {
        int e = base + lane;
        unsigned vmine = (e < end) ? g_ega[e] : 0u;
        int nch = end - base; if (nch > 32) nch = 32;
        int j = 0;
        for (; j + 3 < nch; j += 4) {
            unsigned va = __shfl_sync(0xffffffffu, vmine, j);
            unsigned vb = __shfl_sync(0xffffffffu, vmine, j + 1);
            unsigned vc = __shfl_sync(0xffffffffu, vmine, j + 2);
            unsigned vd = __shfl_sync(0xffffffffu, vmine, j + 3);
            float sa = __shfl_sync(0xffffffffu, myinv, (int)(va & 7u));
            float sb = __shfl_sync(0xffffffffu, myinv, (int)(vb & 7u));
            float sc = __shfl_sync(0xffffffffu, myinv, (int)(vc & 7u));
            float sd = __shfl_sync(0xffffffffu, myinv, (int)(vd & 7u));
            gacc2(va, sa, lane, acc);
            gacc2(vb, sb, lane, acc);
            gacc2(vc, sc, lane, acc);
            gacc2(vd, sd, lane, acc);
        }
        for (; j < nch; j++) {
            unsigned va = __shfl_sync(0xffffffffu, vmine, j);
            float sa = __shfl_sync(0xffffffffu, myinv, (int)(va & 7u));
            gacc2(va, sa, lane, acc);
        }
    }

    float2 root = ((const float2*)&g_root2[(size_t)d * 64])[lane];
    float2 v = make_float2(root.x + acc.x, root.y + acc.y);
    *(float2*)(&out[(size_t)d * F_OUT + lane * 2]) = v;
}

// ---------------- launch -----------------------------------------------------
extern "C" void kernel_launch(void* const* d_in, const int* in_sizes, int n_in,
                              void* d_out, int out_size) {
    const float* x     = (const float*)d_in[0];
    const int*   ei    = (const int*)d_in[1];   // [2, E] int32 (JAX x64 disabled)
    const int*   et    = (const int*)d_in[2];   // [E]    int32
    const float* W1    = (const float*)d_in[3];
    const float* root1 = (const float*)d_in[4];
    const float* b1    = (const float*)d_in[5];
    const float* W2    = (const float*)d_in[6];
    const float* root2 = (const float*)d_in[7];
    const float* b2    = (const float*)d_in[8];
    float*       out   = (float*)d_out;

    const int N = in_sizes[0] / F_IN;
    const int E = in_sizes[2];
    const int* src = ei;
    const int* dst = ei + E;
    const int tilesM = (N + 127) / 128;

    static bool attr_done = false;
    if (!attr_done) {
        cudaFuncSetAttribute(k_gemm_hmma, cudaFuncAttributeMaxDynamicSharedMemorySize, DSMEM);
        attr_done = true;
    }

    // 1: combo prep (split_x + packB1 + packB2 + zero dcnt)
    {
        int total = N * 128 + NC1 * 128 + NPAD2 * 128 + N;
        k_combo<<<(total + 255) / 256, 256>>>(x, root1, W1, root2, W2, N);
    }
    // 2-3: CSR count + scan
    k_count<<<(E + 255) / 256, 256>>>(dst, E);
    k_scan<<<1, 1024>>>(N);

    // 4: layer-1 GEMM (captured by ncu)
    {
        dim3 grid(NC1 / 128, tilesM);
        k_gemm_hmma<<<grid, 256, DSMEM>>>(1, b1, N, F_HID);
    }

    // 5: CSR fill
    k_fill<<<(E + 255) / 256, 256>>>(src, dst, et, E);

    // 6: scatter1 (fused mean + relu + split)
    k_scatter1<<<(N * 32 + 255) / 256, 256>>>(N);

    // 7: layer-2 GEMM
    {
        dim3 grid(NPAD2 / 128, tilesM);
        k_gemm_hmma<<<grid, 256, DSMEM>>>(2, b2, N, F_OUT);
    }

    // 8: scatter2 (fused mean + final output write)
    k_scatter2<<<(N * 32 + 255) / 256, 256>>>(out, N);
}

// round 11
// speedup vs baseline: 3.1558x; 1.1490x over previous
#include <cuda_runtime.h>
#include <cuda_bf16.h>
#include <cuda_fp16.h>
#include <cstdint>

// Problem constants (fixed by the dataset).
#define NNODES   50000
#define NEDGES   800000
#define F_IN     128
#define F_HID    128
#define F_OUT    64
#define NREL     8
#define NC1      1152     // 128 root + 8*128 messages (layer 1 packed cols)
#define NC2      576      // 64 root + 8*64 (layer 2)
#define NPAD2    640      // NC2 padded to multiple of 128

// ---------------- scratch (static device globals; no allocation) -------------
__device__ __align__(128) float  g_root1[(size_t)NNODES * 128];   // 25.6 MB fp32
__device__ __align__(128) __half g_msg1 [(size_t)NNODES * 1024];  // 102.4 MB fp16
__device__ __align__(128) float  g_root2[(size_t)NNODES * 64];    // 12.8 MB fp32
__device__ __align__(128) __half g_msg2 [(size_t)NNODES * 512];   // 51.2 MB fp16
__device__ __align__(256) __nv_bfloat16 g_Ahi[(size_t)NNODES * 128];
__device__ __align__(256) __nv_bfloat16 g_Alo[(size_t)NNODES * 128];
__device__ __align__(256) __nv_bfloat16 g_B1hi[NC1 * 128];   // transposed Bt[n][k]
__device__ __align__(256) __nv_bfloat16 g_B1lo[NC1 * 128];
__device__ __align__(256) __nv_bfloat16 g_B2hi[NPAD2 * 128];
__device__ __align__(256) __nv_bfloat16 g_B2lo[NPAD2 * 128];
// edge CSR (by dst) structures
__device__ int      g_dcnt[NNODES];  // edges per dst
__device__ int      g_ptr [NNODES];  // fill cursor; after fill = row end
__device__ unsigned g_ega[NEDGES];   // src*8 + rel

// ---------------- PTX helpers (plain sm_103-target ISA only) ------------------
__device__ __forceinline__ uint32_t s2u(const void* p) {
    return (uint32_t)__cvta_generic_to_shared(p);
}
__device__ __forceinline__ void ldm_x4(uint32_t* r, uint32_t addr) {
    asm volatile("ldmatrix.sync.aligned.m8n8.x4.shared.b16 {%0,%1,%2,%3}, [%4];"
                 : "=r"(r[0]), "=r"(r[1]), "=r"(r[2]), "=r"(r[3]) : "r"(addr));
}
__device__ __forceinline__ void mma16816(float* c, const uint32_t* a, const uint32_t* b) {
    asm volatile("mma.sync.aligned.m16n8k16.row.col.f32.bf16.bf16.f32 "
                 "{%0,%1,%2,%3}, {%4,%5,%6,%7}, {%8,%9}, {%0,%1,%2,%3};"
                 : "+f"(c[0]), "+f"(c[1]), "+f"(c[2]), "+f"(c[3])
                 : "r"(a[0]), "r"(a[1]), "r"(a[2]), "r"(a[3]), "r"(b[0]), "r"(b[1]));
}
__device__ __forceinline__ void cpa16(uint32_t dst, const void* src, bool pred) {
    int sz = pred ? 16 : 0;
    asm volatile("cp.async.cg.shared.global [%0], [%1], 16, %2;"
                 :: "r"(dst), "l"(src), "r"(sz) : "memory");
}
struct BF4 { __nv_bfloat162 a, b; };   // 8-byte packed store of 4 bf16

// fp16 message-row gather helpers
__device__ __forceinline__ void gacc1(unsigned v, float s, int lane, float4& acc) {
    const __half* bp = &g_msg1[(size_t)(v >> 3) * 1024 + (size_t)(v & 7u) * 128];
    uint2 u = *(const uint2*)(bp + lane * 4);
    __half2 h0 = *reinterpret_cast<__half2*>(&u.x);
    __half2 h1 = *reinterpret_cast<__half2*>(&u.y);
    float2 f0 = __half22float2(h0), f1 = __half22float2(h1);
    acc.x += f0.x * s; acc.y += f0.y * s; acc.z += f1.x * s; acc.w += f1.y * s;
}
__device__ __forceinline__ void gacc2(unsigned v, float s, int lane, float2& acc) {
    const __half* bp = &g_msg2[(size_t)(v >> 3) * 512 + (size_t)(v & 7u) * 64];
    __half2 h = *(const __half2*)(bp + lane * 2);
    float2 f = __half22float2(h);
    acc.x += f.x * s; acc.y += f.y * s;
}

// ---------------- combo prep: split_x + packB1 + packB2 -----------------------
__global__ void k_combo(const float* __restrict__ x,
                        const float* __restrict__ root1, const float* __restrict__ W1,
                        const float* __restrict__ root2, const float* __restrict__ W2,
                        int N) {
    int i = blockIdx.x * blockDim.x + threadIdx.x;
    int splitTot = N * 128;
    if (i < splitTot) {
        float v = x[i];
        __nv_bfloat16 h = __float2bfloat16(v);
        g_Ahi[i] = h;
        g_Alo[i] = __float2bfloat16(v - __bfloat162float(h));
        return;
    }
    int j = i - splitTot;
    if (j < NC1 * 128) {
        int n = j >> 7, k = j & 127;
        float v;
        if (n < F_HID) v = root1[k * F_HID + n];
        else {
            int r = (n - F_HID) >> 7, jj = (n - F_HID) & 127;
            v = W1[((size_t)r * F_IN + k) * F_HID + jj];
        }
        __nv_bfloat16 h = __float2bfloat16(v);
        g_B1hi[j] = h;
        g_B1lo[j] = __float2bfloat16(v - __bfloat162float(h));
        return;
    }
    int j2 = j - NC1 * 128;
    if (j2 < NPAD2 * 128) {
        int n = j2 >> 7, k = j2 & 127;
        float v = 0.0f;
        if (n < NC2) {
            if (n < F_OUT) v = root2[k * F_OUT + n];
            else {
                int r = (n - F_OUT) >> 6, jj = (n - F_OUT) & 63;
                v = W2[((size_t)r * F_HID + k) * F_OUT + jj];
            }
        }
        __nv_bfloat16 h = __float2bfloat16(v);
        g_B2hi[j2] = h;
        g_B2lo[j2] = __float2bfloat16(v - __bfloat162float(h));
    }
}

// ---------------- graph-structure kernels (side stream) -----------------------
__global__ void k_zerod(int n) {
    int i = blockIdx.x * blockDim.x + threadIdx.x;
    if (i < n) g_dcnt[i] = 0;
}
__global__ void k_count(const int* __restrict__ dst, int E) {
    int e = blockIdx.x * blockDim.x + threadIdx.x;
    if (e >= E) return;
    atomicAdd(&g_dcnt[dst[e]], 1);
}
// single-block exclusive scan of g_dcnt -> g_ptr (n <= 50176)
__global__ void k_scan(int n) {
    __shared__ int part[1024];
    int t = threadIdx.x;
    const int CH = (n + 1023) / 1024;
    int base = t * CH;
    int s = 0;
    for (int i = 0; i < CH; i++) { int idx = base + i; if (idx < n) s += g_dcnt[idx]; }
    part[t] = s;
    __syncthreads();
    for (int off = 1; off < 1024; off <<= 1) {
        int v = (t >= off) ? part[t - off] : 0;
        __syncthreads();
        part[t] += v;
        __syncthreads();
    }
    int excl = (t == 0) ? 0 : part[t - 1];
    for (int i = 0; i < CH; i++) {
        int idx = base + i;
        if (idx < n) { g_ptr[idx] = excl; excl += g_dcnt[idx]; }
    }
}
__global__ void k_fill(const int* __restrict__ src, const int* __restrict__ dst,
                       const int* __restrict__ et, int E) {
    int e = blockIdx.x * blockDim.x + threadIdx.x;
    if (e >= E) return;
    int pos = atomicAdd(&g_ptr[dst[e]], 1);
    g_ega[pos] = (unsigned)(src[e] * NREL + et[e]);
}

// ---------------- bf16-split HMMA GEMM, cp.async 2-stage pipeline -------------
#define TS 40                 // bf16 per SMEM row (32 data + 8 pad)
#define TILE_B (128 * TS * 2) // 10240 bytes per tile
#define DSMEM  (2 * 4 * TILE_B)

__global__ __launch_bounds__(256, 2)
void k_gemm_hmma(int b_sel, const float* __restrict__ bias,
                 int M, int biasN) {
    extern __shared__ char dynsm[];
    __shared__ float sBias[128];

    const __nv_bfloat16* gBhi = (b_sel == 1) ? &g_B1hi[0] : &g_B2hi[0];
    const __nv_bfloat16* gBlo = (b_sel == 1) ? &g_B1lo[0] : &g_B2lo[0];

    const int tid  = threadIdx.x;
    const int wid  = tid >> 5;
    const int lane = tid & 31;
    const int wm   = wid & 1;
    const int wn   = wid >> 1;
    const int n0 = blockIdx.x * 128;
    const int m0 = blockIdx.y * 128;

    const uint32_t smBase = s2u(dynsm);

    if (tid < 128) {
        int gc = n0 + tid;
        sBias[tid] = (gc < biasN) ? bias[gc] : 0.0f;
    }

    float acc[4][4][4];
#pragma unroll
    for (int i = 0; i < 4; i++)
#pragma unroll
        for (int j = 0; j < 4; j++)
#pragma unroll
            for (int q = 0; q < 4; q++) acc[i][j][q] = 0.0f;

    const int aRow = wm * 64 + (lane & 15);
    const int aCol = ((lane >> 4) & 1) * 8;
    const int bRow = wn * 32 + (lane & 7) + ((lane & 16) ? 8 : 0);
    const int bCol = (lane & 8) ? 8 : 0;

    auto issue_chunk = [&](int kc, int st) {
        const int kbase = kc * 32;
        const uint32_t stBase = smBase + (uint32_t)(st * 4 * TILE_B);
#pragma unroll
        for (int c = tid; c < 512; c += 256) {
            int r = c >> 2, ch = c & 3;
            int gm = m0 + r;
            bool pa = gm < M;
            int gmc = pa ? gm : 0;
            int gn = n0 + r;  // B rows padded to tile grid; always valid
            uint32_t so = (uint32_t)(r * TS + ch * 8) * 2;
            cpa16(stBase + 0 * TILE_B + so, &g_Ahi[(size_t)gmc * 128 + kbase + ch * 8], pa);
            cpa16(stBase + 1 * TILE_B + so, &g_Alo[(size_t)gmc * 128 + kbase + ch * 8], pa);
            cpa16(stBase + 2 * TILE_B + so, &gBhi[(size_t)gn * 128 + kbase + ch * 8], true);
            cpa16(stBase + 3 * TILE_B + so, &gBlo[(size_t)gn * 128 + kbase + ch * 8], true);
        }
        asm volatile("cp.async.commit_group;" ::: "memory");
    };

    issue_chunk(0, 0);

#pragma unroll 1
    for (int kc = 0; kc < 4; kc++) {
        const int st = kc & 1;
        if (kc < 3) {
            issue_chunk(kc + 1, st ^ 1);
            asm volatile("cp.async.wait_group 1;" ::: "memory");
        } else {
            asm volatile("cp.async.wait_group 0;" ::: "memory");
        }
        __syncthreads();

        const uint32_t stBase = smBase + (uint32_t)(st * 4 * TILE_B);
        const uint32_t asHi = stBase, asLo = stBase + TILE_B;
        const uint32_t bsHi = stBase + 2 * TILE_B, bsLo = stBase + 3 * TILE_B;

#pragma unroll
        for (int ks = 0; ks < 2; ks++) {
            uint32_t bh[4][2], bl[4][2];
            {
                uint32_t t[4];
                ldm_x4(t, bsHi + (uint32_t)(bRow * TS + ks * 16 + bCol) * 2);
                bh[0][0] = t[0]; bh[0][1] = t[1]; bh[1][0] = t[2]; bh[1][1] = t[3];
                ldm_x4(t, bsHi + (uint32_t)((bRow + 16) * TS + ks * 16 + bCol) * 2);
                bh[2][0] = t[0]; bh[2][1] = t[1]; bh[3][0] = t[2]; bh[3][1] = t[3];
                ldm_x4(t, bsLo + (uint32_t)(bRow * TS + ks * 16 + bCol) * 2);
                bl[0][0] = t[0]; bl[0][1] = t[1]; bl[1][0] = t[2]; bl[1][1] = t[3];
                ldm_x4(t, bsLo + (uint32_t)((bRow + 16) * TS + ks * 16 + bCol) * 2);
                bl[2][0] = t[0]; bl[2][1] = t[1]; bl[3][0] = t[2]; bl[3][1] = t[3];
            }
#pragma unroll
            for (int mt = 0; mt < 4; mt++) {
                uint32_t ah[4], al[4];
                ldm_x4(ah, asHi + (uint32_t)((aRow + mt * 16) * TS + ks * 16 + aCol) * 2);
                ldm_x4(al, asLo + (uint32_t)((aRow + mt * 16) * TS + ks * 16 + aCol) * 2);
#pragma unroll
                for (int nt = 0; nt < 4; nt++) {
                    mma16816(acc[mt][nt], ah, bh[nt]);
                    mma16816(acc[mt][nt], ah, bl[nt]);
                    mma16816(acc[mt][nt], al, bh[nt]);
                }
            }
        }
        __syncthreads();
    }

    // epilogue: root cols -> fp32 buffers, message cols -> fp16 buffers
    const int quad = lane >> 2, tq = lane & 3;
#pragma unroll
    for (int mt = 0; mt < 4; mt++) {
        int row = m0 + wm * 64 + mt * 16 + quad;
#pragma unroll
        for (int nt = 0; nt < 4; nt++) {
            int colL = wn * 32 + nt * 8 + tq * 2;
            int gc = n0 + colL;
            float b0 = sBias[colL], b1v = sBias[colL + 1];
            float2 v0 = make_float2(acc[mt][nt][0] + b0, acc[mt][nt][1] + b1v);
            float2 v1 = make_float2(acc[mt][nt][2] + b0, acc[mt][nt][3] + b1v);
            if (b_sel == 1) {
                if (n0 == 0) {
                    if (row < M)     *(float2*)&g_root1[(size_t)row * 128 + gc] = v0;
                    if (row + 8 < M) *(float2*)&g_root1[(size_t)(row + 8) * 128 + gc] = v1;
                } else {
                    int mc = gc - 128;
                    if (row < M)
                        *(__half2*)&g_msg1[(size_t)row * 1024 + mc] = __floats2half2_rn(v0.x, v0.y);
                    if (row + 8 < M)
                        *(__half2*)&g_msg1[(size_t)(row + 8) * 1024 + mc] = __floats2half2_rn(v1.x, v1.y);
                }
            } else {
                if (gc < 64) {
                    if (row < M)     *(float2*)&g_root2[(size_t)row * 64 + gc] = v0;
                    if (row + 8 < M) *(float2*)&g_root2[(size_t)(row + 8) * 64 + gc] = v1;
                } else if (gc < NC2) {
                    int mc = gc - 64;
                    if (row < M)
                        *(__half2*)&g_msg2[(size_t)row * 512 + mc] = __floats2half2_rn(v0.x, v0.y);
                    if (row + 8 < M)
                        *(__half2*)&g_msg2[(size_t)(row + 8) * 512 + mc] = __floats2half2_rn(v1.x, v1.y);
                }
            }
        }
    }
}

// ---------------- scatter1: warp owns dst; fused mean + relu + bf16 split -----
__global__ void k_scatter1(int N) {
    int d = (blockIdx.x * blockDim.x + threadIdx.x) >> 5;
    int lane = threadIdx.x & 31;
    if (d >= N) return;
    int end = g_ptr[d];
    int beg = end - g_dcnt[d];

    // per-relation counts via ballots (warp-uniform)
    int c0 = 0, c1 = 0, c2 = 0, c3 = 0, c4 = 0, c5 = 0, c6 = 0, c7 = 0;
    for (int base = beg; base < end; base += 32) {
        int e = base + lane;
        int r = (e < end) ? (int)(g_ega[e] & 7u) : -1;
        c0 += __popc(__ballot_sync(0xffffffffu, r == 0));
        c1 += __popc(__ballot_sync(0xffffffffu, r == 1));
        c2 += __popc(__ballot_sync(0xffffffffu, r == 2));
        c3 += __popc(__ballot_sync(0xffffffffu, r == 3));
        c4 += __popc(__ballot_sync(0xffffffffu, r == 4));
        c5 += __popc(__ballot_sync(0xffffffffu, r == 5));
        c6 += __popc(__ballot_sync(0xffffffffu, r == 6));
        c7 += __popc(__ballot_sync(0xffffffffu, r == 7));
    }
    int myc = (lane == 0) ? c0 : (lane == 1) ? c1 : (lane == 2) ? c2 : (lane == 3) ? c3
            : (lane == 4) ? c4 : (lane == 5) ? c5 : (lane == 6) ? c6 : (lane == 7) ? c7 : 1;
    float myinv = 1.0f / (float)(myc > 1 ? myc : 1);

    // gather + accumulate (4-way unroll; scale via shfl from lane rel)
    float4 acc = make_float4(0.f, 0.f, 0.f, 0.f);
    for (int base = beg; base < end; base += 32) {
        int e = base + lane;
        unsigned vmine = (e < end) ? g_ega[e] : 0u;
        int nch = end - base; if (nch > 32) nch = 32;
        int j = 0;
        for (; j + 3 < nch; j += 4) {
            unsigned va = __shfl_sync(0xffffffffu, vmine, j);
            unsigned vb = __shfl_sync(0xffffffffu, vmine, j + 1);
            unsigned vc = __shfl_sync(0xffffffffu, vmine, j + 2);
            unsigned vd = __shfl_sync(0xffffffffu, vmine, j + 3);
            float sa = __shfl_sync(0xffffffffu, myinv, (int)(va & 7u));
            float sb = __shfl_sync(0xffffffffu, myinv, (int)(vb & 7u));
            float sc = __shfl_sync(0xffffffffu, myinv, (int)(vc & 7u));
            float sd = __shfl_sync(0xffffffffu, myinv, (int)(vd & 7u));
            gacc1(va, sa, lane, acc);
            gacc1(vb, sb, lane, acc);
            gacc1(vc, sc, lane, acc);
            gacc1(vd, sd, lane, acc);
        }
        for (; j < nch; j++) {
            unsigned va = __shfl_sync(0xffffffffu, vmine, j);
            float sa = __shfl_sync(0xffffffffu, myinv, (int)(va & 7u));
            gacc1(va, sa, lane, acc);
        }
    }

    // fused epilogue: add root row, relu, bf16 hi/lo split -> g_Ahi/g_Alo
    float4 root = ((const float4*)&g_root1[(size_t)d * 128])[lane];
    float f[4] = { root.x + acc.x, root.y + acc.y, root.z + acc.z, root.w + acc.w };
    __nv_bfloat16 hi[4], lo[4];
#pragma unroll
    for (int q = 0; q < 4; q++) {
        float v = f[q] > 0.0f ? f[q] : 0.0f;
        hi[q] = __float2bfloat16(v);
        lo[q] = __float2bfloat16(v - __bfloat162float(hi[q]));
    }
    BF4 wh, wl;
    wh.a = __halves2bfloat162(hi[0], hi[1]); wh.b = __halves2bfloat162(hi[2], hi[3]);
    wl.a = __halves2bfloat162(lo[0], lo[1]); wl.b = __halves2bfloat162(lo[2], lo[3]);
    *reinterpret_cast<BF4*>(&g_Ahi[(size_t)d * 128 + lane * 4]) = wh;
    *reinterpret_cast<BF4*>(&g_Alo[(size_t)d * 128 + lane * 4]) = wl;
}

// ---------------- scatter2: warp owns dst; fused mean + output write ----------
__global__ void k_scatter2(float* __restrict__ out, int N) {
    int d = (blockIdx.x * blockDim.x + threadIdx.x) >> 5;
    int lane = threadIdx.x & 31;
    if (d >= N) return;
    int end = g_ptr[d];
    int beg = end - g_dcnt[d];

    int c0 = 0, c1 = 0, c2 = 0, c3 = 0, c4 = 0, c5 = 0, c6 = 0, c7 = 0;
    for (int base = beg; base < end; base += 32) {
        int e = base + lane;
        int r = (e < end) ? (int)(g_ega[e] & 7u) : -1;
        c0 += __popc(__ballot_sync(0xffffffffu, r == 0));
        c1 += __popc(__ballot_sync(0xffffffffu, r == 1));
        c2 += __popc(__ballot_sync(0xffffffffu, r == 2));
        c3 += __popc(__ballot_sync(0xffffffffu, r == 3));
        c4 += __popc(__ballot_sync(0xffffffffu, r == 4));
        c5 += __popc(__ballot_sync(0xffffffffu, r == 5));
        c6 += __popc(__ballot_sync(0xffffffffu, r == 6));
        c7 += __popc(__ballot_sync(0xffffffffu, r == 7));
    }
    int myc = (lane == 0) ? c0 : (lane == 1) ? c1 : (lane == 2) ? c2 : (lane == 3) ? c3
            : (lane == 4) ? c4 : (lane == 5) ? c5 : (lane == 6) ? c6 : (lane == 7) ? c7 : 1;
    float myinv = 1.0f / (float)(myc > 1 ? myc : 1);

    float2 acc = make_float2(0.f, 0.f);
    for (int base = beg; base < end; base += 32) {
        int e = base + lane;
        unsigned vmine = (e < end) ? g_ega[e] : 0u;
        int nch = end - base; if (nch > 32) nch = 32;
        int j = 0;
        for (; j + 3 < nch; j += 4) {
            unsigned va = __shfl_sync(0xffffffffu, vmine, j);
            unsigned vb = __shfl_sync(0xffffffffu, vmine, j + 1);
            unsigned vc = __shfl_sync(0xffffffffu, vmine, j + 2);
            unsigned vd = __shfl_sync(0xffffffffu, vmine, j + 3);
            float sa = __shfl_sync(0xffffffffu, myinv, (int)(va & 7u));
            float sb = __shfl_sync(0xffffffffu, myinv, (int)(vb & 7u));
            float sc = __shfl_sync(0xffffffffu, myinv, (int)(vc & 7u));
            float sd = __shfl_sync(0xffffffffu, myinv, (int)(vd & 7u));
            gacc2(va, sa, lane, acc);
            gacc2(vb, sb, lane, acc);
            gacc2(vc, sc, lane, acc);
            gacc2(vd, sd, lane, acc);
        }
        for (; j < nch; j++) {
            unsigned va = __shfl_sync(0xffffffffu, vmine, j);
            float sa = __shfl_sync(0xffffffffu, myinv, (int)(va & 7u));
            gacc2(va, sa, lane, acc);
        }
    }

    float2 root = ((const float2*)&g_root2[(size_t)d * 64])[lane];
    float2 v = make_float2(root.x + acc.x, root.y + acc.y);
    *(float2*)(&out[(size_t)d * F_OUT + lane * 2]) = v;
}

// ---------------- launch -----------------------------------------------------
extern "C" void kernel_launch(void* const* d_in, const int* in_sizes, int n_in,
                              void* d_out, int out_size) {
    const float* x     = (const float*)d_in[0];
    const int*   ei    = (const int*)d_in[1];   // [2, E] int32 (JAX x64 disabled)
    const int*   et    = (const int*)d_in[2];   // [E]    int32
    const float* W1    = (const float*)d_in[3];
    const float* root1 = (const float*)d_in[4];
    const float* b1    = (const float*)d_in[5];
    const float* W2    = (const float*)d_in[6];
    const float* root2 = (const float*)d_in[7];
    const float* b2    = (const float*)d_in[8];
    float*       out   = (float*)d_out;

    const int N = in_sizes[0] / F_IN;
    const int E = in_sizes[2];
    const int* src = ei;
    const int* dst = ei + E;
    const int tilesM = (N + 127) / 128;

    static cudaStream_t s2 = nullptr;
    static cudaEvent_t evFork = nullptr, evJoin = nullptr;
    if (!s2) {
        cudaStreamCreateWithFlags(&s2, cudaStreamNonBlocking);
        cudaEventCreateWithFlags(&evFork, cudaEventDisableTiming);
        cudaEventCreateWithFlags(&evJoin, cudaEventDisableTiming);
        cudaFuncSetAttribute(k_gemm_hmma, cudaFuncAttributeMaxDynamicSharedMemorySize, DSMEM);
    }

    // fork: side stream builds CSR while main stream runs combo + GEMM1
    cudaEventRecord(evFork, 0);
    cudaStreamWaitEvent(s2, evFork, 0);

    // side chain (s2): zero dcnt -> count -> scan -> fill
    k_zerod<<<(N + 255) / 256, 256, 0, s2>>>(N);
    k_count<<<(E + 255) / 256, 256, 0, s2>>>(dst, E);
    k_scan<<<1, 1024, 0, s2>>>(N);
    k_fill<<<(E + 255) / 256, 256, 0, s2>>>(src, dst, et, E);
    cudaEventRecord(evJoin, s2);

    // main chain: combo prep -> layer-1 GEMM
    {
        int total = N * 128 + NC1 * 128 + NPAD2 * 128;
        k_combo<<<(total + 255) / 256, 256>>>(x, root1, W1, root2, W2, N);
    }
    {
        dim3 grid(NC1 / 128, tilesM);
        k_gemm_hmma<<<grid, 256, DSMEM>>>(1, b1, N, F_HID);
    }

    // join: scatter1 needs both GEMM1 (main) and fill (side)
    cudaStreamWaitEvent(0, evJoin, 0);

    k_scatter1<<<(N * 32 + 255) / 256, 256>>>(N);
    {
        dim3 grid(NPAD2 / 128, tilesM);
        k_gemm_hmma<<<grid, 256, DSMEM>>>(2, b2, N, F_OUT);
    }
    k_scatter2<<<(N * 32 + 255) / 256, 256>>>(out, N);
}